// round 12
// baseline (speedup 1.0000x reference)
#include <cuda_runtime.h>
#include <cuda_fp16.h>
#include <cstdint>

// Problem constants
#define Bc    4
#define Mc    4096
#define HIDc  1024
#define Hc    16
#define HDc   64
#define NSEGc 32
#define SCALEc 0.125f

// ---------------------------------------------------------------------------
// Static device scratch (allocation-free per harness rules)
// ---------------------------------------------------------------------------
__device__ __half g_qkv_hi[(size_t)3 * Bc * Hc * Mc * HDc];  // [c][b][h][m][d]
__device__ __half g_xhi[(size_t)Bc * Mc * HIDc];
__device__ __half g_wqkv_hi[(size_t)3 * HIDc * HIDc];
__device__ __half g_wout_hi[(size_t)HIDc * HIDc];
__device__ __half g_attn_hi[(size_t)Bc * Mc * HIDc];

// ===========================================================================
// Helpers
// ===========================================================================
__device__ __forceinline__ uint32_t smem_u32(const void* p) {
    uint32_t a;
    asm("{ .reg .u64 t; cvta.to.shared.u64 t, %1; cvt.u32.u64 %0, t; }"
        : "=r"(a) : "l"(p));
    return a;
}

__device__ __forceinline__ void ldsm_x4(uint32_t* r, uint32_t addr) {
    asm volatile("ldmatrix.sync.aligned.m8n8.x4.shared.b16 {%0,%1,%2,%3}, [%4];"
                 : "=r"(r[0]), "=r"(r[1]), "=r"(r[2]), "=r"(r[3]) : "r"(addr));
}
__device__ __forceinline__ void ldsm_x4_t(uint32_t* r, uint32_t addr) {
    asm volatile("ldmatrix.sync.aligned.m8n8.x4.trans.shared.b16 {%0,%1,%2,%3}, [%4];"
                 : "=r"(r[0]), "=r"(r[1]), "=r"(r[2]), "=r"(r[3]) : "r"(addr));
}

__device__ __forceinline__ void mma_f16(float* c, const uint32_t* a,
                                        uint32_t b0, uint32_t b1) {
    asm volatile(
        "mma.sync.aligned.m16n8k16.row.col.f32.f16.f16.f32 "
        "{%0,%1,%2,%3}, {%4,%5,%6,%7}, {%8,%9}, {%0,%1,%2,%3};"
        : "+f"(c[0]), "+f"(c[1]), "+f"(c[2]), "+f"(c[3])
        : "r"(a[0]), "r"(a[1]), "r"(a[2]), "r"(a[3]), "r"(b0), "r"(b1));
}

__device__ __forceinline__ void cp_async16(uint32_t dst, const void* src) {
    asm volatile("cp.async.cg.shared.global [%0], [%1], 16;"
                 :: "r"(dst), "l"(src) : "memory");
}
#define CP_COMMIT() asm volatile("cp.async.commit_group;" ::: "memory")
#define CP_WAIT0()  asm volatile("cp.async.wait_group 0;" ::: "memory")

__device__ __forceinline__ uint32_t pack_f16(float x, float y) {
    __half2 v = __halves2half2(__float2half_rn(x), __float2half_rn(y));
    return *reinterpret_cast<uint32_t*>(&v);
}

// ===========================================================================
// Pre-split kernel: fp32 -> fp16
// ===========================================================================
__global__ __launch_bounds__(256) void split_kernel(const float* __restrict__ src,
                                                    __half* __restrict__ hi,
                                                    int n4) {
    const int i = blockIdx.x * 256 + threadIdx.x;
    if (i >= n4) return;
    const float4 v = ((const float4*)src)[i];
    ((__half2*)hi)[2 * i]     = __halves2half2(__float2half_rn(v.x), __float2half_rn(v.y));
    ((__half2*)hi)[2 * i + 1] = __halves2half2(__float2half_rn(v.z), __float2half_rn(v.w));
}

// ===========================================================================
// fp16 1-term tensor GEMM: C = Ahi·Whi^T.
// 128x64 CTA tile (occupancy experiment: ~80 regs -> 3 CTAs/SM, 24 warps/SM).
// K-chunk 64 (128 B rows, stride 144 B), 256 threads, warps 4(m) x 2(n),
// warp tile 32x32. 2-stage cp.async, 1 barrier/iter.
// MODE 0: epilogue scatters fp16 into g_qkv_hi.  MODE 1: fp32 row-major out.
// ===========================================================================
#define TK        64
#define NITER     (HIDc / TK)              // 16
#define LDSTR     72                       // fp16 elems per SMEM row (144 B)
#define TILE_A_B  (128 * LDSTR * 2)        // 18432 B
#define TILE_B_B  (64 * LDSTR * 2)         // 9216 B
#define STAGE_B   (TILE_A_B + TILE_B_B)    // 27648 B
#define GEMM_SMEM (2 * STAGE_B)            // 55296 B

template <int MODE>
__global__ __launch_bounds__(256, 3) void tgemm_kernel(
        const __half* __restrict__ Ahi_g, const __half* __restrict__ Bhi_g,
        float* __restrict__ Cout) {
    extern __shared__ __align__(16) char smraw[];
    const uint32_t smb = smem_u32(smraw);

    const int tid  = threadIdx.x;
    const int wid  = tid >> 5;
    const int lane = tid & 31;
    const int row0 = blockIdx.y * 128;
    const int col0 = blockIdx.x * 64;
    const int warp_m = wid & 3;
    const int warp_n = wid >> 2;

    // ---- cp.async mapping: A = 4 chunks/thread, B = 2 chunks/thread ----
    uint32_t offA[4], relA[4], offB[2], relB[2];
#pragma unroll
    for (int t = 0; t < 4; t++) {
        const int ci  = tid + 256 * t;
        const int row = ci >> 3;            // 0..127
        const int c16 = ci & 7;
        offA[t] = (uint32_t)((row0 + row) * HIDc + c16 * 8);
        relA[t] = (uint32_t)(row * (LDSTR * 2) + c16 * 16);
    }
#pragma unroll
    for (int t = 0; t < 2; t++) {
        const int ci  = tid + 256 * t;
        const int row = ci >> 3;            // 0..63
        const int c16 = ci & 7;
        offB[t] = (uint32_t)((col0 + row) * HIDc + c16 * 8);
        relB[t] = (uint32_t)(TILE_A_B + row * (LDSTR * 2) + c16 * 16);
    }

    const int sub = lane >> 3;
    const int r8  = lane & 7;
    uint32_t a_lm[2], b_lm[2];
#pragma unroll
    for (int mt = 0; mt < 2; mt++) {
        const int row = warp_m * 32 + mt * 16 + (sub & 1) * 8 + r8;
        a_lm[mt] = smb + row * (LDSTR * 2) + (sub >> 1) * 16;
    }
#pragma unroll
    for (int np = 0; np < 2; np++) {
        const int row = warp_n * 32 + np * 16 + (sub >> 1) * 8 + r8;
        b_lm[np] = smb + TILE_A_B + row * (LDSTR * 2) + (sub & 1) * 16;
    }

    float acc[2][4][4];
#pragma unroll
    for (int i = 0; i < 2; i++)
#pragma unroll
        for (int j = 0; j < 4; j++)
#pragma unroll
            for (int q = 0; q < 4; q++) acc[i][j][q] = 0.0f;

    // ---- prologue: stage 0 ----
#pragma unroll
    for (int t = 0; t < 4; t++) cp_async16(smb + relA[t], Ahi_g + offA[t]);
#pragma unroll
    for (int t = 0; t < 2; t++) cp_async16(smb + relB[t], Bhi_g + offB[t]);
    CP_COMMIT();

    for (int it = 0; it < NITER; it++) {
        CP_WAIT0();
        __syncthreads();
        const uint32_t stg = (uint32_t)(it & 1) * STAGE_B;

        // issue next stage into the other buffer (overlaps MMA phase)
        if (it + 1 < NITER) {
            const uint32_t nst = smb + (uint32_t)((it + 1) & 1) * STAGE_B;
            const uint32_t k0 = (uint32_t)(it + 1) * TK;
#pragma unroll
            for (int t = 0; t < 4; t++) cp_async16(nst + relA[t], Ahi_g + offA[t] + k0);
#pragma unroll
            for (int t = 0; t < 2; t++) cp_async16(nst + relB[t], Bhi_g + offB[t] + k0);
            CP_COMMIT();
        }

#pragma unroll
        for (int k16 = 0; k16 < 4; k16++) {
            const uint32_t kb = stg + k16 * 32;
            uint32_t Ah[2][4], Bf[2][4];
#pragma unroll
            for (int mt = 0; mt < 2; mt++) ldsm_x4(Ah[mt], a_lm[mt] + kb);
#pragma unroll
            for (int np = 0; np < 2; np++) ldsm_x4(Bf[np], b_lm[np] + kb);
#pragma unroll
            for (int mt = 0; mt < 2; mt++)
#pragma unroll
                for (int np = 0; np < 2; np++) {
                    mma_f16(acc[mt][2 * np],     Ah[mt], Bf[np][0], Bf[np][1]);
                    mma_f16(acc[mt][2 * np + 1], Ah[mt], Bf[np][2], Bf[np][3]);
                }
        }
    }

    // ---- epilogue ----
    const int rbase = row0 + warp_m * 32 + (lane >> 2);
    const int cbase = col0 + warp_n * 32 + 2 * (lane & 3);
#pragma unroll
    for (int mt = 0; mt < 2; mt++) {
#pragma unroll
        for (int nt = 0; nt < 4; nt++) {
            const int c = cbase + nt * 8;
#pragma unroll
            for (int half = 0; half < 2; half++) {
                const int r = rbase + mt * 16 + half * 8;
                const float vx = acc[mt][nt][2 * half];
                const float vy = acc[mt][nt][2 * half + 1];
                if (MODE == 0) {
                    const int b  = r >> 12;
                    const int m  = r & 4095;
                    const int cc = c >> 10;
                    const int h  = (c & 1023) >> 6;
                    const int d  = c & 63;
                    const size_t idx = (size_t)cc * (Bc * Hc * Mc * HDc) +
                        (((size_t)b * Hc + h) * Mc + m) * HDc + d;
                    *(uint32_t*)&g_qkv_hi[idx] = pack_f16(vx, vy);
                } else {
                    *(float2*)&Cout[(size_t)r * HIDc + c] = make_float2(vx, vy);
                }
            }
        }
    }
}

// ===========================================================================
// Tensor-core attention (fp16 1-term): one block per (seg,h,b), 8 warps.
// S = Qh·Kh^T, in-register masked softmax, out = Ph·Vh.
// SMEM: gather Qh@0, Kh@18432, Vh@36864.
//       P overlay: Ph@0 (stride 272B, 34816 B, over Qh/Kh after S-phase).
// ===========================================================================
#define ATT_SMEM 55296

__global__ __launch_bounds__(256, 2) void attn_kernel(const int* __restrict__ hmap) {
    const int seg = blockIdx.x;
    const int h   = blockIdx.y;
    const int b   = blockIdx.z;

    extern __shared__ __align__(16) char smraw[];
    const uint32_t smb = smem_u32(smraw);
    __shared__ int toks[128];

    const int tid  = threadIdx.x;
    const int warp = tid >> 5;
    const int lane = tid & 31;

    if (tid < 128) toks[tid] = hmap[seg * 128 + tid];
    __syncthreads();

    // ---- gather: 3 parts (Qh,Kh,Vh) x 128 rows x 8 x 16B ----
#pragma unroll
    for (int n = 0; n < 12; n++) {
        const int c   = tid + 256 * n;
        const int p   = c >> 10;              // 0=Q, 1=K, 2=V
        const int rem = c & 1023;
        const int row = rem >> 3;
        const int ch  = rem & 7;
        const __half* s = g_qkv_hi + (size_t)p * (Bc * Hc * Mc * HDc) +
            (((size_t)b * Hc + h) * Mc + toks[row]) * HDc + ch * 8;
        cp_async16(smb + (uint32_t)p * 18432u + (uint32_t)(row * 144 + ch * 16), s);
    }
    CP_COMMIT();
    CP_WAIT0();
    __syncthreads();

    const int w16 = warp * 16;
    const int sub = lane >> 3;
    const int r8  = lane & 7;

    // ---- S = Qh Kh^T ----
    const uint32_t aq = smb + (uint32_t)((w16 + (sub & 1) * 8 + r8) * 144 + (sub >> 1) * 16);
    uint32_t bk[8];
#pragma unroll
    for (int np = 0; np < 8; np++)
        bk[np] = smb + 18432u + (uint32_t)((np * 16 + (sub >> 1) * 8 + r8) * 144 + (sub & 1) * 16);

    float s_acc[16][4];
#pragma unroll
    for (int j = 0; j < 16; j++)
#pragma unroll
        for (int q = 0; q < 4; q++) s_acc[j][q] = 0.0f;

#pragma unroll
    for (int kt = 0; kt < 4; kt++) {
        const uint32_t kb = kt * 32;
        uint32_t Ah[4], Bf[8][4];
        ldsm_x4(Ah, aq + kb);
#pragma unroll
        for (int np = 0; np < 8; np++) ldsm_x4(Bf[np], bk[np] + kb);
#pragma unroll
        for (int np = 0; np < 8; np++) {
            mma_f16(s_acc[2 * np],     Ah, Bf[np][0], Bf[np][1]);
            mma_f16(s_acc[2 * np + 1], Ah, Bf[np][2], Bf[np][3]);
        }
    }

    // ---- masked softmax in fragment registers ----
    const bool oddrow = ((lane >> 2) & 1) != 0;
    float mx0 = -1e30f, mx1 = -1e30f;
#pragma unroll
    for (int j = 0; j < 16; j++) {
#pragma unroll
        for (int q = 0; q < 4; q++) s_acc[j][q] *= SCALEc;
        if (oddrow) { s_acc[j][1] = -1e30f; s_acc[j][3] = -1e30f; }
        mx0 = fmaxf(mx0, fmaxf(s_acc[j][0], s_acc[j][1]));
        mx1 = fmaxf(mx1, fmaxf(s_acc[j][2], s_acc[j][3]));
    }
    mx0 = fmaxf(mx0, __shfl_xor_sync(0xffffffffu, mx0, 1));
    mx0 = fmaxf(mx0, __shfl_xor_sync(0xffffffffu, mx0, 2));
    mx1 = fmaxf(mx1, __shfl_xor_sync(0xffffffffu, mx1, 1));
    mx1 = fmaxf(mx1, __shfl_xor_sync(0xffffffffu, mx1, 2));

    float sum0 = 0.f, sum1 = 0.f;
#pragma unroll
    for (int j = 0; j < 16; j++) {
        s_acc[j][0] = __expf(s_acc[j][0] - mx0);
        s_acc[j][1] = __expf(s_acc[j][1] - mx0);
        s_acc[j][2] = __expf(s_acc[j][2] - mx1);
        s_acc[j][3] = __expf(s_acc[j][3] - mx1);
        sum0 += s_acc[j][0] + s_acc[j][1];
        sum1 += s_acc[j][2] + s_acc[j][3];
    }
    sum0 += __shfl_xor_sync(0xffffffffu, sum0, 1);
    sum0 += __shfl_xor_sync(0xffffffffu, sum0, 2);
    sum1 += __shfl_xor_sync(0xffffffffu, sum1, 1);
    sum1 += __shfl_xor_sync(0xffffffffu, sum1, 2);
    const float inv0 = 1.0f / sum0;
    const float inv1 = 1.0f / sum1;

    __syncthreads();   // all warps done reading Q/K before P overlay writes

    // ---- store Ph into overlay (stride 272B) ----
    const uint32_t prow = smb + (uint32_t)((w16 + (lane >> 2)) * 272 + (lane & 3) * 4);
#pragma unroll
    for (int j = 0; j < 16; j++) {
        const float p0 = s_acc[j][0] * inv0, p1 = s_acc[j][1] * inv0;
        const float p2 = s_acc[j][2] * inv1, p3 = s_acc[j][3] * inv1;
        const uint32_t o0 = prow + j * 16;
        const uint32_t o1 = o0 + 8 * 272;
        asm volatile("st.shared.b32 [%0], %1;" :: "r"(o0), "r"(pack_f16(p0, p1)) : "memory");
        asm volatile("st.shared.b32 [%0], %1;" :: "r"(o1), "r"(pack_f16(p2, p3)) : "memory");
    }
    __syncthreads();   // P visible to ldmatrix across the block

    // ---- out = Ph · Vh ----
    const uint32_t ap = smb + (uint32_t)((w16 + (lane & 15)) * 272 + (lane >> 4) * 16);
    const int mat = lane >> 3;
    const uint32_t vb = smb + 36864u +
        (uint32_t)(((mat & 1) * 8 + (lane & 7)) * 144 + (mat >> 1) * 16);

    float o_acc[8][4];
#pragma unroll
    for (int j = 0; j < 8; j++)
#pragma unroll
        for (int q = 0; q < 4; q++) o_acc[j][q] = 0.0f;

#pragma unroll
    for (int kt = 0; kt < 8; kt++) {
        uint32_t Ph[4], Vf[4][4];
        ldsm_x4(Ph, ap + kt * 32);
#pragma unroll
        for (int vp = 0; vp < 4; vp++)
            ldsm_x4_t(Vf[vp], vb + (uint32_t)kt * 2304u + vp * 32u);
#pragma unroll
        for (int vp = 0; vp < 4; vp++) {
            mma_f16(o_acc[2 * vp],     Ph, Vf[vp][0], Vf[vp][1]);
            mma_f16(o_acc[2 * vp + 1], Ph, Vf[vp][2], Vf[vp][3]);
        }
    }

    // ---- epilogue: write fp16 attention output ----
    const int r0 = w16 + (lane >> 2);
    const size_t row0g = ((size_t)b * Mc + (size_t)seg * 128 + r0) * HIDc + h * 64;
    const size_t row1g = row0g + 8 * HIDc;
    const int dbase = 2 * (lane & 3);
#pragma unroll
    for (int j = 0; j < 8; j++) {
        const int d = 8 * j + dbase;
        *(uint32_t*)&g_attn_hi[row0g + d] = pack_f16(o_acc[j][0], o_acc[j][1]);
        *(uint32_t*)&g_attn_hi[row1g + d] = pack_f16(o_acc[j][2], o_acc[j][3]);
    }
}

// ===========================================================================
extern "C" void kernel_launch(void* const* d_in, const int* in_sizes, int n_in,
                              void* d_out, int out_size) {
    const float* x     = (const float*)d_in[0];
    const float* w_qkv = (const float*)d_in[1];
    const float* w_out = (const float*)d_in[2];
    const int*   hmap  = (const int*)d_in[3];
    float*       out   = (float*)d_out;

    cudaFuncSetAttribute(tgemm_kernel<0>, cudaFuncAttributeMaxDynamicSharedMemorySize, GEMM_SMEM);
    cudaFuncSetAttribute(tgemm_kernel<1>, cudaFuncAttributeMaxDynamicSharedMemorySize, GEMM_SMEM);
    cudaFuncSetAttribute(attn_kernel,     cudaFuncAttributeMaxDynamicSharedMemorySize, ATT_SMEM);

    __half *xhi, *wqh, *woh, *ahi;
    cudaGetSymbolAddress((void**)&xhi, g_xhi);
    cudaGetSymbolAddress((void**)&wqh, g_wqkv_hi);
    cudaGetSymbolAddress((void**)&woh, g_wout_hi);
    cudaGetSymbolAddress((void**)&ahi, g_attn_hi);

    // Pre-split: all inputs -> fp16
    {
        int n4 = (Bc * Mc * HIDc) / 4;
        split_kernel<<<(n4 + 255) / 256, 256>>>(x, xhi, n4);
        n4 = (3 * HIDc * HIDc) / 4;
        split_kernel<<<(n4 + 255) / 256, 256>>>(w_qkv, wqh, n4);
        n4 = (HIDc * HIDc) / 4;
        split_kernel<<<(n4 + 255) / 256, 256>>>(w_out, woh, n4);
    }
    // QKV projection: 1-term, 128x64 tiles
    {
        dim3 grid(3072 / 64, (Bc * Mc) / 128);          // (48, 128)
        tgemm_kernel<0><<<grid, 256, GEMM_SMEM>>>(xhi, wqh, nullptr);
    }
    // Tensor-core Hilbert attention (1-term)
    {
        dim3 grid(NSEGc, Hc, Bc);
        attn_kernel<<<grid, 256, ATT_SMEM>>>(hmap);
    }
    // Output projection: 1-term, 128x64 tiles
    {
        dim3 grid(HIDc / 64, (Bc * Mc) / 128);          // (16, 128)
        tgemm_kernel<1><<<grid, 256, GEMM_SMEM>>>(ahi, woh, out);
    }
}

// round 13
// speedup vs baseline: 1.1060x; 1.1060x over previous
#include <cuda_runtime.h>
#include <cuda_fp16.h>
#include <cstdint>

// Problem constants
#define Bc    4
#define Mc    4096
#define HIDc  1024
#define Hc    16
#define HDc   64
#define NSEGc 32
#define SCALEc 0.125f

// ---------------------------------------------------------------------------
// Static device scratch (allocation-free per harness rules)
// ---------------------------------------------------------------------------
__device__ __half g_qkv_hi[(size_t)3 * Bc * Hc * Mc * HDc];  // [c][b][h][m][d]
__device__ __half g_xhi[(size_t)Bc * Mc * HIDc];
__device__ __half g_wqkv_hi[(size_t)3 * HIDc * HIDc];
__device__ __half g_wout_hi[(size_t)HIDc * HIDc];
__device__ __half g_attn_hi[(size_t)Bc * Mc * HIDc];

// ===========================================================================
// Helpers
// ===========================================================================
__device__ __forceinline__ uint32_t smem_u32(const void* p) {
    uint32_t a;
    asm("{ .reg .u64 t; cvta.to.shared.u64 t, %1; cvt.u32.u64 %0, t; }"
        : "=r"(a) : "l"(p));
    return a;
}

__device__ __forceinline__ void ldsm_x4(uint32_t* r, uint32_t addr) {
    asm volatile("ldmatrix.sync.aligned.m8n8.x4.shared.b16 {%0,%1,%2,%3}, [%4];"
                 : "=r"(r[0]), "=r"(r[1]), "=r"(r[2]), "=r"(r[3]) : "r"(addr));
}
__device__ __forceinline__ void ldsm_x4_t(uint32_t* r, uint32_t addr) {
    asm volatile("ldmatrix.sync.aligned.m8n8.x4.trans.shared.b16 {%0,%1,%2,%3}, [%4];"
                 : "=r"(r[0]), "=r"(r[1]), "=r"(r[2]), "=r"(r[3]) : "r"(addr));
}

__device__ __forceinline__ void mma_f16(float* c, const uint32_t* a,
                                        uint32_t b0, uint32_t b1) {
    asm volatile(
        "mma.sync.aligned.m16n8k16.row.col.f32.f16.f16.f32 "
        "{%0,%1,%2,%3}, {%4,%5,%6,%7}, {%8,%9}, {%0,%1,%2,%3};"
        : "+f"(c[0]), "+f"(c[1]), "+f"(c[2]), "+f"(c[3])
        : "r"(a[0]), "r"(a[1]), "r"(a[2]), "r"(a[3]), "r"(b0), "r"(b1));
}

__device__ __forceinline__ void cp_async16(uint32_t dst, const void* src) {
    asm volatile("cp.async.cg.shared.global [%0], [%1], 16;"
                 :: "r"(dst), "l"(src) : "memory");
}
#define CP_COMMIT() asm volatile("cp.async.commit_group;" ::: "memory")
#define CP_WAIT0()  asm volatile("cp.async.wait_group 0;" ::: "memory")
#define CP_WAIT1()  asm volatile("cp.async.wait_group 1;" ::: "memory")

__device__ __forceinline__ uint32_t pack_f16(float x, float y) {
    __half2 v = __halves2half2(__float2half_rn(x), __float2half_rn(y));
    return *reinterpret_cast<uint32_t*>(&v);
}

// ===========================================================================
// Pre-split kernel: fp32 -> fp16
// ===========================================================================
__global__ __launch_bounds__(256) void split_kernel(const float* __restrict__ src,
                                                    __half* __restrict__ hi,
                                                    int n4) {
    const int i = blockIdx.x * 256 + threadIdx.x;
    if (i >= n4) return;
    const float4 v = ((const float4*)src)[i];
    ((__half2*)hi)[2 * i]     = __halves2half2(__float2half_rn(v.x), __float2half_rn(v.y));
    ((__half2*)hi)[2 * i + 1] = __halves2half2(__float2half_rn(v.z), __float2half_rn(v.w));
}

// ===========================================================================
// fp16 1-term tensor GEMM: C = Ahi·Whi^T.  (round-11 configuration — best)
// 128x128 tile, K-chunk 64 (128 B rows, stride 144 B -> conflict-free),
// 256 threads, warps 4(m) x 2(n); 3-stage cp.async, 2 tiles/stage.
// MODE 0: epilogue scatters fp16 into g_qkv_hi.  MODE 1: fp32 row-major out.
// ===========================================================================
#define TK        64
#define NITER     (HIDc / TK)              // 16
#define LDSTR     72                       // fp16 elems per SMEM row (144 B)
#define TILE_HB   (128 * LDSTR * 2)        // 18432 B
#define STAGE_B   (2 * TILE_HB)            // 36864 B (A, B)
#define GEMM_SMEM (3 * STAGE_B)            // 110592 B

template <int MODE>
__global__ __launch_bounds__(256, 2) void tgemm_kernel(
        const __half* __restrict__ Ahi_g, const __half* __restrict__ Bhi_g,
        float* __restrict__ Cout) {
    extern __shared__ __align__(16) char smraw[];
    const uint32_t smb = smem_u32(smraw);

    const int tid  = threadIdx.x;
    const int wid  = tid >> 5;
    const int lane = tid & 31;
    const int row0 = blockIdx.y * 128;
    const int col0 = blockIdx.x * 128;
    const int warp_m = wid & 3;
    const int warp_n = wid >> 2;

    // ---- cp.async streams: 8 per thread (2 tiles x 4 chunks) ----
    const __half* src[8];
    uint32_t rel[8];
#pragma unroll
    for (int t = 0; t < 4; t++) {
        const int ci  = tid + 256 * t;
        const int row = ci >> 3;            // 0..127
        const int c16 = ci & 7;             // 16B chunk within 64-elem row
        const size_t offA = (size_t)(row0 + row) * HIDc + c16 * 8;
        const size_t offB = (size_t)(col0 + row) * HIDc + c16 * 8;
        const uint32_t so = (uint32_t)(row * (LDSTR * 2) + c16 * 16);
        src[2 * t + 0] = Ahi_g + offA;  rel[2 * t + 0] = so;
        src[2 * t + 1] = Bhi_g + offB;  rel[2 * t + 1] = TILE_HB + so;
    }

    const int sub = lane >> 3;
    const int r8  = lane & 7;
    uint32_t a_lm[2], b_lm[4];
#pragma unroll
    for (int mt = 0; mt < 2; mt++) {
        const int row = warp_m * 32 + mt * 16 + (sub & 1) * 8 + r8;
        a_lm[mt] = smb + row * (LDSTR * 2) + (sub >> 1) * 16;
    }
#pragma unroll
    for (int np = 0; np < 4; np++) {
        const int row = warp_n * 64 + np * 16 + (sub >> 1) * 8 + r8;
        b_lm[np] = smb + TILE_HB + row * (LDSTR * 2) + (sub & 1) * 16;
    }

    float acc[2][8][4];
#pragma unroll
    for (int i = 0; i < 2; i++)
#pragma unroll
        for (int j = 0; j < 8; j++)
#pragma unroll
            for (int q = 0; q < 4; q++) acc[i][j][q] = 0.0f;

    // ---- prologue: stages 0 and 1 ----
#pragma unroll
    for (int j = 0; j < 8; j++) cp_async16(smb + rel[j], src[j]);
    CP_COMMIT();
#pragma unroll
    for (int j = 0; j < 8; j++) {
        src[j] += TK;
        cp_async16(smb + STAGE_B + rel[j], src[j]);
    }
    CP_COMMIT();

    for (int it = 0; it < NITER; it++) {
        if (it + 1 < NITER) { CP_WAIT1(); } else { CP_WAIT0(); }
        __syncthreads();
        const uint32_t stg = (uint32_t)(it % 3) * STAGE_B;

        if (it + 2 < NITER) {
            const uint32_t nst = smb + (uint32_t)((it + 2) % 3) * STAGE_B;
#pragma unroll
            for (int j = 0; j < 8; j++) {
                src[j] += TK;
                cp_async16(nst + rel[j], src[j]);
            }
            CP_COMMIT();
        }

#pragma unroll
        for (int k16 = 0; k16 < 4; k16++) {
            const uint32_t kb = stg + k16 * 32;
            uint32_t Ah[2][4], Bf[4][4];
#pragma unroll
            for (int mt = 0; mt < 2; mt++) ldsm_x4(Ah[mt], a_lm[mt] + kb);
#pragma unroll
            for (int np = 0; np < 4; np++) ldsm_x4(Bf[np], b_lm[np] + kb);
#pragma unroll
            for (int mt = 0; mt < 2; mt++)
#pragma unroll
                for (int np = 0; np < 4; np++) {
                    mma_f16(acc[mt][2 * np],     Ah[mt], Bf[np][0], Bf[np][1]);
                    mma_f16(acc[mt][2 * np + 1], Ah[mt], Bf[np][2], Bf[np][3]);
                }
        }
    }

    // ---- epilogue ----
    const int rbase = row0 + warp_m * 32 + (lane >> 2);
    const int cbase = col0 + warp_n * 64 + 2 * (lane & 3);
#pragma unroll
    for (int mt = 0; mt < 2; mt++) {
#pragma unroll
        for (int nt = 0; nt < 8; nt++) {
            const int c = cbase + nt * 8;
#pragma unroll
            for (int half = 0; half < 2; half++) {
                const int r = rbase + mt * 16 + half * 8;
                const float vx = acc[mt][nt][2 * half];
                const float vy = acc[mt][nt][2 * half + 1];
                if (MODE == 0) {
                    const int b  = r >> 12;
                    const int m  = r & 4095;
                    const int cc = c >> 10;
                    const int h  = (c & 1023) >> 6;
                    const int d  = c & 63;
                    const size_t idx = (size_t)cc * (Bc * Hc * Mc * HDc) +
                        (((size_t)b * Hc + h) * Mc + m) * HDc + d;
                    *(uint32_t*)&g_qkv_hi[idx] = pack_f16(vx, vy);
                } else {
                    *(float2*)&Cout[(size_t)r * HIDc + c] = make_float2(vx, vy);
                }
            }
        }
    }
}

// ===========================================================================
// Tensor-core attention (fp16 1-term): one block per (seg,h,b), 8 warps.
// S = Qh·Kh^T, in-register masked softmax, out = Ph·Vh.
// SMEM: gather Qh@0, Kh@18432, Vh@36864.
//       P overlay: Ph@0 (stride 272B, 34816 B, over Qh/Kh after S-phase).
// Occupancy experiment: 3 CTAs/SM (attention is phase-serialized, so extra
// CTAs fill the tensor-pipe holes left by gather/softmax phases).
// ===========================================================================
#define ATT_SMEM 55296

__global__ __launch_bounds__(256, 3) void attn_kernel(const int* __restrict__ hmap) {
    const int seg = blockIdx.x;
    const int h   = blockIdx.y;
    const int b   = blockIdx.z;

    extern __shared__ __align__(16) char smraw[];
    const uint32_t smb = smem_u32(smraw);
    __shared__ int toks[128];

    const int tid  = threadIdx.x;
    const int warp = tid >> 5;
    const int lane = tid & 31;

    if (tid < 128) toks[tid] = hmap[seg * 128 + tid];
    __syncthreads();

    // ---- gather: 3 parts (Qh,Kh,Vh) x 128 rows x 8 x 16B ----
#pragma unroll
    for (int n = 0; n < 12; n++) {
        const int c   = tid + 256 * n;
        const int p   = c >> 10;              // 0=Q, 1=K, 2=V
        const int rem = c & 1023;
        const int row = rem >> 3;
        const int ch  = rem & 7;
        const __half* s = g_qkv_hi + (size_t)p * (Bc * Hc * Mc * HDc) +
            (((size_t)b * Hc + h) * Mc + toks[row]) * HDc + ch * 8;
        cp_async16(smb + (uint32_t)p * 18432u + (uint32_t)(row * 144 + ch * 16), s);
    }
    CP_COMMIT();
    CP_WAIT0();
    __syncthreads();

    const int w16 = warp * 16;
    const int sub = lane >> 3;
    const int r8  = lane & 7;

    // ---- S = Qh Kh^T ----
    const uint32_t aq = smb + (uint32_t)((w16 + (sub & 1) * 8 + r8) * 144 + (sub >> 1) * 16);
    uint32_t bk[8];
#pragma unroll
    for (int np = 0; np < 8; np++)
        bk[np] = smb + 18432u + (uint32_t)((np * 16 + (sub >> 1) * 8 + r8) * 144 + (sub & 1) * 16);

    float s_acc[16][4];
#pragma unroll
    for (int j = 0; j < 16; j++)
#pragma unroll
        for (int q = 0; q < 4; q++) s_acc[j][q] = 0.0f;

#pragma unroll
    for (int kt = 0; kt < 4; kt++) {
        const uint32_t kb = kt * 32;
        uint32_t Ah[4], Bf[8][4];
        ldsm_x4(Ah, aq + kb);
#pragma unroll
        for (int np = 0; np < 8; np++) ldsm_x4(Bf[np], bk[np] + kb);
#pragma unroll
        for (int np = 0; np < 8; np++) {
            mma_f16(s_acc[2 * np],     Ah, Bf[np][0], Bf[np][1]);
            mma_f16(s_acc[2 * np + 1], Ah, Bf[np][2], Bf[np][3]);
        }
    }

    // ---- masked softmax in fragment registers ----
    const bool oddrow = ((lane >> 2) & 1) != 0;
    float mx0 = -1e30f, mx1 = -1e30f;
#pragma unroll
    for (int j = 0; j < 16; j++) {
#pragma unroll
        for (int q = 0; q < 4; q++) s_acc[j][q] *= SCALEc;
        if (oddrow) { s_acc[j][1] = -1e30f; s_acc[j][3] = -1e30f; }
        mx0 = fmaxf(mx0, fmaxf(s_acc[j][0], s_acc[j][1]));
        mx1 = fmaxf(mx1, fmaxf(s_acc[j][2], s_acc[j][3]));
    }
    mx0 = fmaxf(mx0, __shfl_xor_sync(0xffffffffu, mx0, 1));
    mx0 = fmaxf(mx0, __shfl_xor_sync(0xffffffffu, mx0, 2));
    mx1 = fmaxf(mx1, __shfl_xor_sync(0xffffffffu, mx1, 1));
    mx1 = fmaxf(mx1, __shfl_xor_sync(0xffffffffu, mx1, 2));

    float sum0 = 0.f, sum1 = 0.f;
#pragma unroll
    for (int j = 0; j < 16; j++) {
        s_acc[j][0] = __expf(s_acc[j][0] - mx0);
        s_acc[j][1] = __expf(s_acc[j][1] - mx0);
        s_acc[j][2] = __expf(s_acc[j][2] - mx1);
        s_acc[j][3] = __expf(s_acc[j][3] - mx1);
        sum0 += s_acc[j][0] + s_acc[j][1];
        sum1 += s_acc[j][2] + s_acc[j][3];
    }
    sum0 += __shfl_xor_sync(0xffffffffu, sum0, 1);
    sum0 += __shfl_xor_sync(0xffffffffu, sum0, 2);
    sum1 += __shfl_xor_sync(0xffffffffu, sum1, 1);
    sum1 += __shfl_xor_sync(0xffffffffu, sum1, 2);
    const float inv0 = 1.0f / sum0;
    const float inv1 = 1.0f / sum1;

    __syncthreads();   // all warps done reading Q/K before P overlay writes

    // ---- store Ph into overlay (stride 272B) ----
    const uint32_t prow = smb + (uint32_t)((w16 + (lane >> 2)) * 272 + (lane & 3) * 4);
#pragma unroll
    for (int j = 0; j < 16; j++) {
        const float p0 = s_acc[j][0] * inv0, p1 = s_acc[j][1] * inv0;
        const float p2 = s_acc[j][2] * inv1, p3 = s_acc[j][3] * inv1;
        const uint32_t o0 = prow + j * 16;
        const uint32_t o1 = o0 + 8 * 272;
        asm volatile("st.shared.b32 [%0], %1;" :: "r"(o0), "r"(pack_f16(p0, p1)) : "memory");
        asm volatile("st.shared.b32 [%0], %1;" :: "r"(o1), "r"(pack_f16(p2, p3)) : "memory");
    }
    __syncthreads();   // P visible to ldmatrix across the block

    // ---- out = Ph · Vh ----
    const uint32_t ap = smb + (uint32_t)((w16 + (lane & 15)) * 272 + (lane >> 4) * 16);
    const int mat = lane >> 3;
    const uint32_t vb = smb + 36864u +
        (uint32_t)(((mat & 1) * 8 + (lane & 7)) * 144 + (mat >> 1) * 16);

    float o_acc[8][4];
#pragma unroll
    for (int j = 0; j < 8; j++)
#pragma unroll
        for (int q = 0; q < 4; q++) o_acc[j][q] = 0.0f;

#pragma unroll
    for (int kt = 0; kt < 8; kt++) {
        uint32_t Ph[4], Vf[4][4];
        ldsm_x4(Ph, ap + kt * 32);
#pragma unroll
        for (int vp = 0; vp < 4; vp++)
            ldsm_x4_t(Vf[vp], vb + (uint32_t)kt * 2304u + vp * 32u);
#pragma unroll
        for (int vp = 0; vp < 4; vp++) {
            mma_f16(o_acc[2 * vp],     Ph, Vf[vp][0], Vf[vp][1]);
            mma_f16(o_acc[2 * vp + 1], Ph, Vf[vp][2], Vf[vp][3]);
        }
    }

    // ---- epilogue: write fp16 attention output ----
    const int r0 = w16 + (lane >> 2);
    const size_t row0g = ((size_t)b * Mc + (size_t)seg * 128 + r0) * HIDc + h * 64;
    const size_t row1g = row0g + 8 * HIDc;
    const int dbase = 2 * (lane & 3);
#pragma unroll
    for (int j = 0; j < 8; j++) {
        const int d = 8 * j + dbase;
        *(uint32_t*)&g_attn_hi[row0g + d] = pack_f16(o_acc[j][0], o_acc[j][1]);
        *(uint32_t*)&g_attn_hi[row1g + d] = pack_f16(o_acc[j][2], o_acc[j][3]);
    }
}

// ===========================================================================
extern "C" void kernel_launch(void* const* d_in, const int* in_sizes, int n_in,
                              void* d_out, int out_size) {
    const float* x     = (const float*)d_in[0];
    const float* w_qkv = (const float*)d_in[1];
    const float* w_out = (const float*)d_in[2];
    const int*   hmap  = (const int*)d_in[3];
    float*       out   = (float*)d_out;

    cudaFuncSetAttribute(tgemm_kernel<0>, cudaFuncAttributeMaxDynamicSharedMemorySize, GEMM_SMEM);
    cudaFuncSetAttribute(tgemm_kernel<1>, cudaFuncAttributeMaxDynamicSharedMemorySize, GEMM_SMEM);
    cudaFuncSetAttribute(attn_kernel,     cudaFuncAttributeMaxDynamicSharedMemorySize, ATT_SMEM);

    __half *xhi, *wqh, *woh, *ahi;
    cudaGetSymbolAddress((void**)&xhi, g_xhi);
    cudaGetSymbolAddress((void**)&wqh, g_wqkv_hi);
    cudaGetSymbolAddress((void**)&woh, g_wout_hi);
    cudaGetSymbolAddress((void**)&ahi, g_attn_hi);

    // Pre-split: all inputs -> fp16
    {
        int n4 = (Bc * Mc * HIDc) / 4;
        split_kernel<<<(n4 + 255) / 256, 256>>>(x, xhi, n4);
        n4 = (3 * HIDc * HIDc) / 4;
        split_kernel<<<(n4 + 255) / 256, 256>>>(w_qkv, wqh, n4);
        n4 = (HIDc * HIDc) / 4;
        split_kernel<<<(n4 + 255) / 256, 256>>>(w_out, woh, n4);
    }
    // QKV projection: 1-term, 128x128 tiles (round-11 config)
    {
        dim3 grid(3072 / 128, (Bc * Mc) / 128);         // (24, 128)
        tgemm_kernel<0><<<grid, 256, GEMM_SMEM>>>(xhi, wqh, nullptr);
    }
    // Tensor-core Hilbert attention (1-term, 3 CTAs/SM)
    {
        dim3 grid(NSEGc, Hc, Bc);
        attn_kernel<<<grid, 256, ATT_SMEM>>>(hmap);
    }
    // Output projection: 1-term, 128x128 tiles
    {
        dim3 grid(HIDc / 128, (Bc * Mc) / 128);         // (8, 128)
        tgemm_kernel<1><<<grid, 256, GEMM_SMEM>>>(ahi, woh, out);
    }
}

// round 14
// speedup vs baseline: 1.1325x; 1.0239x over previous
#include <cuda_runtime.h>
#include <cuda_fp16.h>
#include <cstdint>

// Problem constants
#define Bc    4
#define Mc    4096
#define HIDc  1024
#define Hc    16
#define HDc   64
#define NSEGc 32
#define SCALEc 0.125f

// ---------------------------------------------------------------------------
// Static device scratch (allocation-free per harness rules)
// ---------------------------------------------------------------------------
__device__ __half g_qkv_hi[(size_t)3 * Bc * Hc * Mc * HDc];  // [c][b][h][m][d]
__device__ __half g_xhi[(size_t)Bc * Mc * HIDc];
__device__ __half g_wqkv_hi[(size_t)3 * HIDc * HIDc];
__device__ __half g_wout_hi[(size_t)HIDc * HIDc];
__device__ __half g_attn_hi[(size_t)Bc * Mc * HIDc];

// ===========================================================================
// Helpers
// ===========================================================================
__device__ __forceinline__ uint32_t smem_u32(const void* p) {
    uint32_t a;
    asm("{ .reg .u64 t; cvta.to.shared.u64 t, %1; cvt.u32.u64 %0, t; }"
        : "=r"(a) : "l"(p));
    return a;
}

__device__ __forceinline__ void ldsm_x4(uint32_t* r, uint32_t addr) {
    asm volatile("ldmatrix.sync.aligned.m8n8.x4.shared.b16 {%0,%1,%2,%3}, [%4];"
                 : "=r"(r[0]), "=r"(r[1]), "=r"(r[2]), "=r"(r[3]) : "r"(addr));
}
__device__ __forceinline__ void ldsm_x4_t(uint32_t* r, uint32_t addr) {
    asm volatile("ldmatrix.sync.aligned.m8n8.x4.trans.shared.b16 {%0,%1,%2,%3}, [%4];"
                 : "=r"(r[0]), "=r"(r[1]), "=r"(r[2]), "=r"(r[3]) : "r"(addr));
}

__device__ __forceinline__ void mma_f16(float* c, const uint32_t* a,
                                        uint32_t b0, uint32_t b1) {
    asm volatile(
        "mma.sync.aligned.m16n8k16.row.col.f32.f16.f16.f32 "
        "{%0,%1,%2,%3}, {%4,%5,%6,%7}, {%8,%9}, {%0,%1,%2,%3};"
        : "+f"(c[0]), "+f"(c[1]), "+f"(c[2]), "+f"(c[3])
        : "r"(a[0]), "r"(a[1]), "r"(a[2]), "r"(a[3]), "r"(b0), "r"(b1));
}

__device__ __forceinline__ void cp_async16(uint32_t dst, const void* src) {
    asm volatile("cp.async.cg.shared.global [%0], [%1], 16;"
                 :: "r"(dst), "l"(src) : "memory");
}
#define CP_COMMIT() asm volatile("cp.async.commit_group;" ::: "memory")
#define CP_WAIT0()  asm volatile("cp.async.wait_group 0;" ::: "memory")
#define CP_WAIT1()  asm volatile("cp.async.wait_group 1;" ::: "memory")

__device__ __forceinline__ uint32_t pack_f16(float x, float y) {
    __half2 v = __halves2half2(__float2half_rn(x), __float2half_rn(y));
    return *reinterpret_cast<uint32_t*>(&v);
}

// ===========================================================================
// Fused pre-split kernel: all three fp32 tensors -> fp16 in one launch
// ===========================================================================
#define N4_X  ((Bc * Mc * HIDc) / 4)         // 4194304
#define N4_WQ ((3 * HIDc * HIDc) / 4)        // 786432
#define N4_WO ((HIDc * HIDc) / 4)            // 262144
#define N4_TOTAL (N4_X + N4_WQ + N4_WO)      // 5242880

__global__ __launch_bounds__(256) void split3_kernel(
        const float* __restrict__ x, const float* __restrict__ wq,
        const float* __restrict__ wo) {
    const int i = blockIdx.x * 256 + threadIdx.x;
    if (i >= N4_TOTAL) return;
    const float* src;
    __half* dst;
    int j = i;
    if (j < N4_X) {
        src = x;  dst = g_xhi;
    } else if (j < N4_X + N4_WQ) {
        j -= N4_X;        src = wq; dst = g_wqkv_hi;
    } else {
        j -= N4_X + N4_WQ; src = wo; dst = g_wout_hi;
    }
    const float4 v = ((const float4*)src)[j];
    ((__half2*)dst)[2 * j]     = __halves2half2(__float2half_rn(v.x), __float2half_rn(v.y));
    ((__half2*)dst)[2 * j + 1] = __halves2half2(__float2half_rn(v.z), __float2half_rn(v.w));
}

// ===========================================================================
// fp16 1-term tensor GEMM: C = Ahi·Whi^T.  (round-11/13 configuration — best)
// 128x128 tile, K-chunk 64 (128 B rows, stride 144 B -> conflict-free),
// 256 threads, warps 4(m) x 2(n); 3-stage cp.async, 2 tiles/stage.
// MODE 0: epilogue scatters fp16 into g_qkv_hi.  MODE 1: fp32 row-major out.
// ===========================================================================
#define TK        64
#define NITER     (HIDc / TK)              // 16
#define LDSTR     72                       // fp16 elems per SMEM row (144 B)
#define TILE_HB   (128 * LDSTR * 2)        // 18432 B
#define STAGE_B   (2 * TILE_HB)            // 36864 B (A, B)
#define GEMM_SMEM (3 * STAGE_B)            // 110592 B

template <int MODE>
__global__ __launch_bounds__(256, 2) void tgemm_kernel(
        const __half* __restrict__ Ahi_g, const __half* __restrict__ Bhi_g,
        float* __restrict__ Cout) {
    extern __shared__ __align__(16) char smraw[];
    const uint32_t smb = smem_u32(smraw);

    const int tid  = threadIdx.x;
    const int wid  = tid >> 5;
    const int lane = tid & 31;
    const int row0 = blockIdx.y * 128;
    const int col0 = blockIdx.x * 128;
    const int warp_m = wid & 3;
    const int warp_n = wid >> 2;

    // ---- cp.async streams: 8 per thread (2 tiles x 4 chunks) ----
    const __half* src[8];
    uint32_t rel[8];
#pragma unroll
    for (int t = 0; t < 4; t++) {
        const int ci  = tid + 256 * t;
        const int row = ci >> 3;            // 0..127
        const int c16 = ci & 7;             // 16B chunk within 64-elem row
        const size_t offA = (size_t)(row0 + row) * HIDc + c16 * 8;
        const size_t offB = (size_t)(col0 + row) * HIDc + c16 * 8;
        const uint32_t so = (uint32_t)(row * (LDSTR * 2) + c16 * 16);
        src[2 * t + 0] = Ahi_g + offA;  rel[2 * t + 0] = so;
        src[2 * t + 1] = Bhi_g + offB;  rel[2 * t + 1] = TILE_HB + so;
    }

    const int sub = lane >> 3;
    const int r8  = lane & 7;
    uint32_t a_lm[2], b_lm[4];
#pragma unroll
    for (int mt = 0; mt < 2; mt++) {
        const int row = warp_m * 32 + mt * 16 + (sub & 1) * 8 + r8;
        a_lm[mt] = smb + row * (LDSTR * 2) + (sub >> 1) * 16;
    }
#pragma unroll
    for (int np = 0; np < 4; np++) {
        const int row = warp_n * 64 + np * 16 + (sub >> 1) * 8 + r8;
        b_lm[np] = smb + TILE_HB + row * (LDSTR * 2) + (sub & 1) * 16;
    }

    float acc[2][8][4];
#pragma unroll
    for (int i = 0; i < 2; i++)
#pragma unroll
        for (int j = 0; j < 8; j++)
#pragma unroll
            for (int q = 0; q < 4; q++) acc[i][j][q] = 0.0f;

    // ---- prologue: stages 0 and 1 ----
#pragma unroll
    for (int j = 0; j < 8; j++) cp_async16(smb + rel[j], src[j]);
    CP_COMMIT();
#pragma unroll
    for (int j = 0; j < 8; j++) {
        src[j] += TK;
        cp_async16(smb + STAGE_B + rel[j], src[j]);
    }
    CP_COMMIT();

    for (int it = 0; it < NITER; it++) {
        if (it + 1 < NITER) { CP_WAIT1(); } else { CP_WAIT0(); }
        __syncthreads();
        const uint32_t stg = (uint32_t)(it % 3) * STAGE_B;

        if (it + 2 < NITER) {
            const uint32_t nst = smb + (uint32_t)((it + 2) % 3) * STAGE_B;
#pragma unroll
            for (int j = 0; j < 8; j++) {
                src[j] += TK;
                cp_async16(nst + rel[j], src[j]);
            }
            CP_COMMIT();
        }

#pragma unroll
        for (int k16 = 0; k16 < 4; k16++) {
            const uint32_t kb = stg + k16 * 32;
            uint32_t Ah[2][4], Bf[4][4];
#pragma unroll
            for (int mt = 0; mt < 2; mt++) ldsm_x4(Ah[mt], a_lm[mt] + kb);
#pragma unroll
            for (int np = 0; np < 4; np++) ldsm_x4(Bf[np], b_lm[np] + kb);
#pragma unroll
            for (int mt = 0; mt < 2; mt++)
#pragma unroll
                for (int np = 0; np < 4; np++) {
                    mma_f16(acc[mt][2 * np],     Ah[mt], Bf[np][0], Bf[np][1]);
                    mma_f16(acc[mt][2 * np + 1], Ah[mt], Bf[np][2], Bf[np][3]);
                }
        }
    }

    // ---- epilogue ----
    const int rbase = row0 + warp_m * 32 + (lane >> 2);
    const int cbase = col0 + warp_n * 64 + 2 * (lane & 3);
#pragma unroll
    for (int mt = 0; mt < 2; mt++) {
#pragma unroll
        for (int nt = 0; nt < 8; nt++) {
            const int c = cbase + nt * 8;
#pragma unroll
            for (int half = 0; half < 2; half++) {
                const int r = rbase + mt * 16 + half * 8;
                const float vx = acc[mt][nt][2 * half];
                const float vy = acc[mt][nt][2 * half + 1];
                if (MODE == 0) {
                    const int b  = r >> 12;
                    const int m  = r & 4095;
                    const int cc = c >> 10;
                    const int h  = (c & 1023) >> 6;
                    const int d  = c & 63;
                    const size_t idx = (size_t)cc * (Bc * Hc * Mc * HDc) +
                        (((size_t)b * Hc + h) * Mc + m) * HDc + d;
                    *(uint32_t*)&g_qkv_hi[idx] = pack_f16(vx, vy);
                } else {
                    *(float2*)&Cout[(size_t)r * HIDc + c] = make_float2(vx, vy);
                }
            }
        }
    }
}

// ===========================================================================
// Tensor-core attention (fp16 1-term): one block per (seg,h,b), 8 warps.
// S = Qh·Kh^T, in-register masked softmax, out = Ph·Vh.
// Split gather: Q/K in cp.async group 0, V in group 1 — V latency hides
// under the S-phase MMAs + softmax.
// SMEM: gather Qh@0, Kh@18432, Vh@36864.
//       P overlay: Ph@0 (stride 272B, 34816 B, over Qh/Kh after S-phase).
// ===========================================================================
#define ATT_SMEM 55296

__global__ __launch_bounds__(256, 3) void attn_kernel(const int* __restrict__ hmap) {
    const int seg = blockIdx.x;
    const int h   = blockIdx.y;
    const int b   = blockIdx.z;

    extern __shared__ __align__(16) char smraw[];
    const uint32_t smb = smem_u32(smraw);
    __shared__ int toks[128];

    const int tid  = threadIdx.x;
    const int warp = tid >> 5;
    const int lane = tid & 31;

    if (tid < 128) toks[tid] = hmap[seg * 128 + tid];
    __syncthreads();

    // ---- gather group 0: Qh, Kh (8 chunks/thread) ----
#pragma unroll
    for (int n = 0; n < 8; n++) {
        const int c   = tid + 256 * n;
        const int p   = c >> 10;              // 0=Q, 1=K
        const int rem = c & 1023;
        const int row = rem >> 3;
        const int ch  = rem & 7;
        const __half* s = g_qkv_hi + (size_t)p * (Bc * Hc * Mc * HDc) +
            (((size_t)b * Hc + h) * Mc + toks[row]) * HDc + ch * 8;
        cp_async16(smb + (uint32_t)p * 18432u + (uint32_t)(row * 144 + ch * 16), s);
    }
    CP_COMMIT();
    // ---- gather group 1: Vh (4 chunks/thread) — lands during S phase ----
#pragma unroll
    for (int n = 0; n < 4; n++) {
        const int c   = tid + 256 * n;
        const int row = c >> 3;
        const int ch  = c & 7;
        const __half* s = g_qkv_hi + (size_t)2 * (Bc * Hc * Mc * HDc) +
            (((size_t)b * Hc + h) * Mc + toks[row]) * HDc + ch * 8;
        cp_async16(smb + 36864u + (uint32_t)(row * 144 + ch * 16), s);
    }
    CP_COMMIT();
    CP_WAIT1();    // Q/K landed; V may still be in flight
    __syncthreads();

    const int w16 = warp * 16;
    const int sub = lane >> 3;
    const int r8  = lane & 7;

    // ---- S = Qh Kh^T ----
    const uint32_t aq = smb + (uint32_t)((w16 + (sub & 1) * 8 + r8) * 144 + (sub >> 1) * 16);
    uint32_t bk[8];
#pragma unroll
    for (int np = 0; np < 8; np++)
        bk[np] = smb + 18432u + (uint32_t)((np * 16 + (sub >> 1) * 8 + r8) * 144 + (sub & 1) * 16);

    float s_acc[16][4];
#pragma unroll
    for (int j = 0; j < 16; j++)
#pragma unroll
        for (int q = 0; q < 4; q++) s_acc[j][q] = 0.0f;

#pragma unroll
    for (int kt = 0; kt < 4; kt++) {
        const uint32_t kb = kt * 32;
        uint32_t Ah[4], Bf[8][4];
        ldsm_x4(Ah, aq + kb);
#pragma unroll
        for (int np = 0; np < 8; np++) ldsm_x4(Bf[np], bk[np] + kb);
#pragma unroll
        for (int np = 0; np < 8; np++) {
            mma_f16(s_acc[2 * np],     Ah, Bf[np][0], Bf[np][1]);
            mma_f16(s_acc[2 * np + 1], Ah, Bf[np][2], Bf[np][3]);
        }
    }

    // ---- masked softmax in fragment registers ----
    const bool oddrow = ((lane >> 2) & 1) != 0;
    float mx0 = -1e30f, mx1 = -1e30f;
#pragma unroll
    for (int j = 0; j < 16; j++) {
#pragma unroll
        for (int q = 0; q < 4; q++) s_acc[j][q] *= SCALEc;
        if (oddrow) { s_acc[j][1] = -1e30f; s_acc[j][3] = -1e30f; }
        mx0 = fmaxf(mx0, fmaxf(s_acc[j][0], s_acc[j][1]));
        mx1 = fmaxf(mx1, fmaxf(s_acc[j][2], s_acc[j][3]));
    }
    mx0 = fmaxf(mx0, __shfl_xor_sync(0xffffffffu, mx0, 1));
    mx0 = fmaxf(mx0, __shfl_xor_sync(0xffffffffu, mx0, 2));
    mx1 = fmaxf(mx1, __shfl_xor_sync(0xffffffffu, mx1, 1));
    mx1 = fmaxf(mx1, __shfl_xor_sync(0xffffffffu, mx1, 2));

    float sum0 = 0.f, sum1 = 0.f;
#pragma unroll
    for (int j = 0; j < 16; j++) {
        s_acc[j][0] = __expf(s_acc[j][0] - mx0);
        s_acc[j][1] = __expf(s_acc[j][1] - mx0);
        s_acc[j][2] = __expf(s_acc[j][2] - mx1);
        s_acc[j][3] = __expf(s_acc[j][3] - mx1);
        sum0 += s_acc[j][0] + s_acc[j][1];
        sum1 += s_acc[j][2] + s_acc[j][3];
    }
    sum0 += __shfl_xor_sync(0xffffffffu, sum0, 1);
    sum0 += __shfl_xor_sync(0xffffffffu, sum0, 2);
    sum1 += __shfl_xor_sync(0xffffffffu, sum1, 1);
    sum1 += __shfl_xor_sync(0xffffffffu, sum1, 2);
    const float inv0 = 1.0f / sum0;
    const float inv1 = 1.0f / sum1;

    __syncthreads();   // all warps done reading Q/K before P overlay writes

    // ---- store Ph into overlay (stride 272B) ----
    const uint32_t prow = smb + (uint32_t)((w16 + (lane >> 2)) * 272 + (lane & 3) * 4);
#pragma unroll
    for (int j = 0; j < 16; j++) {
        const float p0 = s_acc[j][0] * inv0, p1 = s_acc[j][1] * inv0;
        const float p2 = s_acc[j][2] * inv1, p3 = s_acc[j][3] * inv1;
        const uint32_t o0 = prow + j * 16;
        const uint32_t o1 = o0 + 8 * 272;
        asm volatile("st.shared.b32 [%0], %1;" :: "r"(o0), "r"(pack_f16(p0, p1)) : "memory");
        asm volatile("st.shared.b32 [%0], %1;" :: "r"(o1), "r"(pack_f16(p2, p3)) : "memory");
    }
    CP_WAIT0();        // V landed (usually long ago)
    __syncthreads();   // P + V visible to ldmatrix across the block

    // ---- out = Ph · Vh ----
    const uint32_t ap = smb + (uint32_t)((w16 + (lane & 15)) * 272 + (lane >> 4) * 16);
    const int mat = lane >> 3;
    const uint32_t vb = smb + 36864u +
        (uint32_t)(((mat & 1) * 8 + (lane & 7)) * 144 + (mat >> 1) * 16);

    float o_acc[8][4];
#pragma unroll
    for (int j = 0; j < 8; j++)
#pragma unroll
        for (int q = 0; q < 4; q++) o_acc[j][q] = 0.0f;

#pragma unroll
    for (int kt = 0; kt < 8; kt++) {
        uint32_t Ph[4], Vf[4][4];
        ldsm_x4(Ph, ap + kt * 32);
#pragma unroll
        for (int vp = 0; vp < 4; vp++)
            ldsm_x4_t(Vf[vp], vb + (uint32_t)kt * 2304u + vp * 32u);
#pragma unroll
        for (int vp = 0; vp < 4; vp++) {
            mma_f16(o_acc[2 * vp],     Ph, Vf[vp][0], Vf[vp][1]);
            mma_f16(o_acc[2 * vp + 1], Ph, Vf[vp][2], Vf[vp][3]);
        }
    }

    // ---- epilogue: write fp16 attention output ----
    const int r0 = w16 + (lane >> 2);
    const size_t row0g = ((size_t)b * Mc + (size_t)seg * 128 + r0) * HIDc + h * 64;
    const size_t row1g = row0g + 8 * HIDc;
    const int dbase = 2 * (lane & 3);
#pragma unroll
    for (int j = 0; j < 8; j++) {
        const int d = 8 * j + dbase;
        *(uint32_t*)&g_attn_hi[row0g + d] = pack_f16(o_acc[j][0], o_acc[j][1]);
        *(uint32_t*)&g_attn_hi[row1g + d] = pack_f16(o_acc[j][2], o_acc[j][3]);
    }
}

// ===========================================================================
extern "C" void kernel_launch(void* const* d_in, const int* in_sizes, int n_in,
                              void* d_out, int out_size) {
    const float* x     = (const float*)d_in[0];
    const float* w_qkv = (const float*)d_in[1];
    const float* w_out = (const float*)d_in[2];
    const int*   hmap  = (const int*)d_in[3];
    float*       out   = (float*)d_out;

    cudaFuncSetAttribute(tgemm_kernel<0>, cudaFuncAttributeMaxDynamicSharedMemorySize, GEMM_SMEM);
    cudaFuncSetAttribute(tgemm_kernel<1>, cudaFuncAttributeMaxDynamicSharedMemorySize, GEMM_SMEM);
    cudaFuncSetAttribute(attn_kernel,     cudaFuncAttributeMaxDynamicSharedMemorySize, ATT_SMEM);

    __half *xhi, *wqh, *woh, *ahi;
    cudaGetSymbolAddress((void**)&xhi, g_xhi);
    cudaGetSymbolAddress((void**)&wqh, g_wqkv_hi);
    cudaGetSymbolAddress((void**)&woh, g_wout_hi);
    cudaGetSymbolAddress((void**)&ahi, g_attn_hi);

    // Fused pre-split: x, w_qkv, w_out -> fp16 in one launch
    split3_kernel<<<(N4_TOTAL + 255) / 256, 256>>>(x, w_qkv, w_out);

    // QKV projection: 1-term, 128x128 tiles
    {
        dim3 grid(3072 / 128, (Bc * Mc) / 128);         // (24, 128)
        tgemm_kernel<0><<<grid, 256, GEMM_SMEM>>>(xhi, wqh, nullptr);
    }
    // Tensor-core Hilbert attention (split-gather overlap)
    {
        dim3 grid(NSEGc, Hc, Bc);
        attn_kernel<<<grid, 256, ATT_SMEM>>>(hmap);
    }
    // Output projection: 1-term, 128x128 tiles
    {
        dim3 grid(HIDc / 128, (Bc * Mc) / 128);         // (8, 128)
        tgemm_kernel<1><<<grid, 256, GEMM_SMEM>>>(ahi, woh, out);
    }
}

// round 15
// speedup vs baseline: 1.2088x; 1.0674x over previous
#include <cuda_runtime.h>
#include <cuda_fp16.h>
#include <cstdint>

// Problem constants
#define Bc    4
#define Mc    4096
#define HIDc  1024
#define Hc    16
#define HDc   64
#define NSEGc 32
#define SCALEc 0.125f

// ---------------------------------------------------------------------------
// Static device scratch (allocation-free per harness rules)
// ---------------------------------------------------------------------------
__device__ __half g_qkv_hi[(size_t)3 * Bc * Hc * Mc * HDc];  // [c][b][h][m][d]
__device__ __half g_xhi[(size_t)Bc * Mc * HIDc];
__device__ __half g_wqkv_hi[(size_t)3 * HIDc * HIDc];
__device__ __half g_wout_hi[(size_t)HIDc * HIDc];
__device__ __half g_attn_hi[(size_t)Bc * Mc * HIDc];

// ===========================================================================
// Helpers
// ===========================================================================
__device__ __forceinline__ uint32_t smem_u32(const void* p) {
    uint32_t a;
    asm("{ .reg .u64 t; cvta.to.shared.u64 t, %1; cvt.u32.u64 %0, t; }"
        : "=r"(a) : "l"(p));
    return a;
}

__device__ __forceinline__ void ldsm_x4(uint32_t* r, uint32_t addr) {
    asm volatile("ldmatrix.sync.aligned.m8n8.x4.shared.b16 {%0,%1,%2,%3}, [%4];"
                 : "=r"(r[0]), "=r"(r[1]), "=r"(r[2]), "=r"(r[3]) : "r"(addr));
}
__device__ __forceinline__ void ldsm_x4_t(uint32_t* r, uint32_t addr) {
    asm volatile("ldmatrix.sync.aligned.m8n8.x4.trans.shared.b16 {%0,%1,%2,%3}, [%4];"
                 : "=r"(r[0]), "=r"(r[1]), "=r"(r[2]), "=r"(r[3]) : "r"(addr));
}

__device__ __forceinline__ void mma_f16(float* c, const uint32_t* a,
                                        uint32_t b0, uint32_t b1) {
    asm volatile(
        "mma.sync.aligned.m16n8k16.row.col.f32.f16.f16.f32 "
        "{%0,%1,%2,%3}, {%4,%5,%6,%7}, {%8,%9}, {%0,%1,%2,%3};"
        : "+f"(c[0]), "+f"(c[1]), "+f"(c[2]), "+f"(c[3])
        : "r"(a[0]), "r"(a[1]), "r"(a[2]), "r"(a[3]), "r"(b0), "r"(b1));
}

__device__ __forceinline__ void cp_async16(uint32_t dst, const void* src) {
    asm volatile("cp.async.cg.shared.global [%0], [%1], 16;"
                 :: "r"(dst), "l"(src) : "memory");
}
#define CP_COMMIT() asm volatile("cp.async.commit_group;" ::: "memory")
#define CP_WAIT0()  asm volatile("cp.async.wait_group 0;" ::: "memory")
#define CP_WAIT1()  asm volatile("cp.async.wait_group 1;" ::: "memory")

__device__ __forceinline__ uint32_t pack_f16(float x, float y) {
    __half2 v = __halves2half2(__float2half_rn(x), __float2half_rn(y));
    return *reinterpret_cast<uint32_t*>(&v);
}

// ===========================================================================
// Fused pre-split kernel: all three fp32 tensors -> fp16, 8 elems/thread
// ===========================================================================
#define N4_X  ((Bc * Mc * HIDc) / 4)         // 4194304
#define N4_WQ ((3 * HIDc * HIDc) / 4)        // 786432
#define N4_WO ((HIDc * HIDc) / 4)            // 262144
#define N4_TOTAL (N4_X + N4_WQ + N4_WO)      // 5242880
#define N8_TOTAL (N4_TOTAL / 2)              // 2621440 (all counts even)

__global__ __launch_bounds__(256) void split3_kernel(
        const float* __restrict__ x, const float* __restrict__ wq,
        const float* __restrict__ wo) {
    const int i8 = blockIdx.x * 256 + threadIdx.x;
    if (i8 >= N8_TOTAL) return;
#pragma unroll
    for (int k = 0; k < 2; k++) {
        int j = 2 * i8 + k;
        const float* src;
        __half* dst;
        if (j < N4_X) {
            src = x;  dst = g_xhi;
        } else if (j < N4_X + N4_WQ) {
            j -= N4_X;         src = wq; dst = g_wqkv_hi;
        } else {
            j -= N4_X + N4_WQ; src = wo; dst = g_wout_hi;
        }
        const float4 v = ((const float4*)src)[j];
        ((__half2*)dst)[2 * j]     = __halves2half2(__float2half_rn(v.x), __float2half_rn(v.y));
        ((__half2*)dst)[2 * j + 1] = __halves2half2(__float2half_rn(v.z), __float2half_rn(v.w));
    }
}

// ===========================================================================
// fp16 1-term tensor GEMM: C = Ahi·Whi^T.
// 128x128 tile, K-chunk 64 (128 B rows, stride 144 B -> conflict-free),
// 256 threads, warps 4(m) x 2(n); 3-stage cp.async, 2 tiles/stage.
// cp.async for the next stage is issued AFTER the first k16 batch so the
// tensor pipe starts immediately post-barrier.
// MODE 0: epilogue scatters fp16 into g_qkv_hi.  MODE 1: fp32 row-major out.
// ===========================================================================
#define TK        64
#define NITER     (HIDc / TK)              // 16
#define LDSTR     72                       // fp16 elems per SMEM row (144 B)
#define TILE_HB   (128 * LDSTR * 2)        // 18432 B
#define STAGE_B   (2 * TILE_HB)            // 36864 B (A, B)
#define GEMM_SMEM (3 * STAGE_B)            // 110592 B

template <int MODE>
__global__ __launch_bounds__(256, 2) void tgemm_kernel(
        const __half* __restrict__ Ahi_g, const __half* __restrict__ Bhi_g,
        float* __restrict__ Cout) {
    extern __shared__ __align__(16) char smraw[];
    const uint32_t smb = smem_u32(smraw);

    const int tid  = threadIdx.x;
    const int wid  = tid >> 5;
    const int lane = tid & 31;
    const int row0 = blockIdx.y * 128;
    const int col0 = blockIdx.x * 128;
    const int warp_m = wid & 3;
    const int warp_n = wid >> 2;

    // ---- cp.async streams: 8 per thread (2 tiles x 4 chunks) ----
    const __half* src[8];
    uint32_t rel[8];
#pragma unroll
    for (int t = 0; t < 4; t++) {
        const int ci  = tid + 256 * t;
        const int row = ci >> 3;            // 0..127
        const int c16 = ci & 7;             // 16B chunk within 64-elem row
        const size_t offA = (size_t)(row0 + row) * HIDc + c16 * 8;
        const size_t offB = (size_t)(col0 + row) * HIDc + c16 * 8;
        const uint32_t so = (uint32_t)(row * (LDSTR * 2) + c16 * 16);
        src[2 * t + 0] = Ahi_g + offA;  rel[2 * t + 0] = so;
        src[2 * t + 1] = Bhi_g + offB;  rel[2 * t + 1] = TILE_HB + so;
    }

    const int sub = lane >> 3;
    const int r8  = lane & 7;
    uint32_t a_lm[2], b_lm[4];
#pragma unroll
    for (int mt = 0; mt < 2; mt++) {
        const int row = warp_m * 32 + mt * 16 + (sub & 1) * 8 + r8;
        a_lm[mt] = smb + row * (LDSTR * 2) + (sub >> 1) * 16;
    }
#pragma unroll
    for (int np = 0; np < 4; np++) {
        const int row = warp_n * 64 + np * 16 + (sub >> 1) * 8 + r8;
        b_lm[np] = smb + TILE_HB + row * (LDSTR * 2) + (sub & 1) * 16;
    }

    float acc[2][8][4];
#pragma unroll
    for (int i = 0; i < 2; i++)
#pragma unroll
        for (int j = 0; j < 8; j++)
#pragma unroll
            for (int q = 0; q < 4; q++) acc[i][j][q] = 0.0f;

    auto do_k16 = [&](uint32_t kb) {
        uint32_t Ah[2][4], Bf[4][4];
#pragma unroll
        for (int mt = 0; mt < 2; mt++) ldsm_x4(Ah[mt], a_lm[mt] + kb);
#pragma unroll
        for (int np = 0; np < 4; np++) ldsm_x4(Bf[np], b_lm[np] + kb);
#pragma unroll
        for (int mt = 0; mt < 2; mt++)
#pragma unroll
            for (int np = 0; np < 4; np++) {
                mma_f16(acc[mt][2 * np],     Ah[mt], Bf[np][0], Bf[np][1]);
                mma_f16(acc[mt][2 * np + 1], Ah[mt], Bf[np][2], Bf[np][3]);
            }
    };

    // ---- prologue: stages 0 and 1 ----
#pragma unroll
    for (int j = 0; j < 8; j++) cp_async16(smb + rel[j], src[j]);
    CP_COMMIT();
#pragma unroll
    for (int j = 0; j < 8; j++) {
        src[j] += TK;
        cp_async16(smb + STAGE_B + rel[j], src[j]);
    }
    CP_COMMIT();

    for (int it = 0; it < NITER; it++) {
        if (it + 1 < NITER) { CP_WAIT1(); } else { CP_WAIT0(); }
        __syncthreads();
        const uint32_t stg = (uint32_t)(it % 3) * STAGE_B;

        // first k16 immediately: tensor pipe fills right after the barrier
        do_k16(stg);

        // issue next stage while MMAs run
        if (it + 2 < NITER) {
            const uint32_t nst = smb + (uint32_t)((it + 2) % 3) * STAGE_B;
#pragma unroll
            for (int j = 0; j < 8; j++) {
                src[j] += TK;
                cp_async16(nst + rel[j], src[j]);
            }
            CP_COMMIT();
        }

        do_k16(stg + 32);
        do_k16(stg + 64);
        do_k16(stg + 96);
    }

    // ---- epilogue ----
    const int rbase = row0 + warp_m * 32 + (lane >> 2);
    const int cbase = col0 + warp_n * 64 + 2 * (lane & 3);
#pragma unroll
    for (int mt = 0; mt < 2; mt++) {
#pragma unroll
        for (int nt = 0; nt < 8; nt++) {
            const int c = cbase + nt * 8;
#pragma unroll
            for (int half = 0; half < 2; half++) {
                const int r = rbase + mt * 16 + half * 8;
                const float vx = acc[mt][nt][2 * half];
                const float vy = acc[mt][nt][2 * half + 1];
                if (MODE == 0) {
                    const int b  = r >> 12;
                    const int m  = r & 4095;
                    const int cc = c >> 10;
                    const int h  = (c & 1023) >> 6;
                    const int d  = c & 63;
                    const size_t idx = (size_t)cc * (Bc * Hc * Mc * HDc) +
                        (((size_t)b * Hc + h) * Mc + m) * HDc + d;
                    *(uint32_t*)&g_qkv_hi[idx] = pack_f16(vx, vy);
                } else {
                    *(float2*)&Cout[(size_t)r * HIDc + c] = make_float2(vx, vy);
                }
            }
        }
    }
}

// ===========================================================================
// Tensor-core attention (fp16 1-term): one block per (seg,h,b), 8 warps.
// S = Qh·Kh^T, in-register masked softmax, out = Ph·Vh.
// Split gather: Q/K in cp.async group 0, V in group 1 — V latency hides
// under the S-phase MMAs + softmax.
// SMEM: gather Qh@0, Kh@18432, Vh@36864.
//       P overlay: Ph@0 (stride 272B, 34816 B, over Qh/Kh after S-phase).
// ===========================================================================
#define ATT_SMEM 55296

__global__ __launch_bounds__(256, 3) void attn_kernel(const int* __restrict__ hmap) {
    const int seg = blockIdx.x;
    const int h   = blockIdx.y;
    const int b   = blockIdx.z;

    extern __shared__ __align__(16) char smraw[];
    const uint32_t smb = smem_u32(smraw);
    __shared__ int toks[128];

    const int tid  = threadIdx.x;
    const int warp = tid >> 5;
    const int lane = tid & 31;

    if (tid < 128) toks[tid] = hmap[seg * 128 + tid];
    __syncthreads();

    // ---- gather group 0: Qh, Kh (8 chunks/thread) ----
#pragma unroll
    for (int n = 0; n < 8; n++) {
        const int c   = tid + 256 * n;
        const int p   = c >> 10;              // 0=Q, 1=K
        const int rem = c & 1023;
        const int row = rem >> 3;
        const int ch  = rem & 7;
        const __half* s = g_qkv_hi + (size_t)p * (Bc * Hc * Mc * HDc) +
            (((size_t)b * Hc + h) * Mc + toks[row]) * HDc + ch * 8;
        cp_async16(smb + (uint32_t)p * 18432u + (uint32_t)(row * 144 + ch * 16), s);
    }
    CP_COMMIT();
    // ---- gather group 1: Vh (4 chunks/thread) — lands during S phase ----
#pragma unroll
    for (int n = 0; n < 4; n++) {
        const int c   = tid + 256 * n;
        const int row = c >> 3;
        const int ch  = c & 7;
        const __half* s = g_qkv_hi + (size_t)2 * (Bc * Hc * Mc * HDc) +
            (((size_t)b * Hc + h) * Mc + toks[row]) * HDc + ch * 8;
        cp_async16(smb + 36864u + (uint32_t)(row * 144 + ch * 16), s);
    }
    CP_COMMIT();
    CP_WAIT1();    // Q/K landed; V may still be in flight
    __syncthreads();

    const int w16 = warp * 16;
    const int sub = lane >> 3;
    const int r8  = lane & 7;

    // ---- S = Qh Kh^T ----
    const uint32_t aq = smb + (uint32_t)((w16 + (sub & 1) * 8 + r8) * 144 + (sub >> 1) * 16);
    uint32_t bk[8];
#pragma unroll
    for (int np = 0; np < 8; np++)
        bk[np] = smb + 18432u + (uint32_t)((np * 16 + (sub >> 1) * 8 + r8) * 144 + (sub & 1) * 16);

    float s_acc[16][4];
#pragma unroll
    for (int j = 0; j < 16; j++)
#pragma unroll
        for (int q = 0; q < 4; q++) s_acc[j][q] = 0.0f;

#pragma unroll
    for (int kt = 0; kt < 4; kt++) {
        const uint32_t kb = kt * 32;
        uint32_t Ah[4], Bf[8][4];
        ldsm_x4(Ah, aq + kb);
#pragma unroll
        for (int np = 0; np < 8; np++) ldsm_x4(Bf[np], bk[np] + kb);
#pragma unroll
        for (int np = 0; np < 8; np++) {
            mma_f16(s_acc[2 * np],     Ah, Bf[np][0], Bf[np][1]);
            mma_f16(s_acc[2 * np + 1], Ah, Bf[np][2], Bf[np][3]);
        }
    }

    // ---- masked softmax in fragment registers ----
    const bool oddrow = ((lane >> 2) & 1) != 0;
    float mx0 = -1e30f, mx1 = -1e30f;
#pragma unroll
    for (int j = 0; j < 16; j++) {
#pragma unroll
        for (int q = 0; q < 4; q++) s_acc[j][q] *= SCALEc;
        if (oddrow) { s_acc[j][1] = -1e30f; s_acc[j][3] = -1e30f; }
        mx0 = fmaxf(mx0, fmaxf(s_acc[j][0], s_acc[j][1]));
        mx1 = fmaxf(mx1, fmaxf(s_acc[j][2], s_acc[j][3]));
    }
    mx0 = fmaxf(mx0, __shfl_xor_sync(0xffffffffu, mx0, 1));
    mx0 = fmaxf(mx0, __shfl_xor_sync(0xffffffffu, mx0, 2));
    mx1 = fmaxf(mx1, __shfl_xor_sync(0xffffffffu, mx1, 1));
    mx1 = fmaxf(mx1, __shfl_xor_sync(0xffffffffu, mx1, 2));

    float sum0 = 0.f, sum1 = 0.f;
#pragma unroll
    for (int j = 0; j < 16; j++) {
        s_acc[j][0] = __expf(s_acc[j][0] - mx0);
        s_acc[j][1] = __expf(s_acc[j][1] - mx0);
        s_acc[j][2] = __expf(s_acc[j][2] - mx1);
        s_acc[j][3] = __expf(s_acc[j][3] - mx1);
        sum0 += s_acc[j][0] + s_acc[j][1];
        sum1 += s_acc[j][2] + s_acc[j][3];
    }
    sum0 += __shfl_xor_sync(0xffffffffu, sum0, 1);
    sum0 += __shfl_xor_sync(0xffffffffu, sum0, 2);
    sum1 += __shfl_xor_sync(0xffffffffu, sum1, 1);
    sum1 += __shfl_xor_sync(0xffffffffu, sum1, 2);
    const float inv0 = 1.0f / sum0;
    const float inv1 = 1.0f / sum1;

    __syncthreads();   // all warps done reading Q/K before P overlay writes

    // ---- store Ph into overlay (stride 272B) ----
    const uint32_t prow = smb + (uint32_t)((w16 + (lane >> 2)) * 272 + (lane & 3) * 4);
#pragma unroll
    for (int j = 0; j < 16; j++) {
        const float p0 = s_acc[j][0] * inv0, p1 = s_acc[j][1] * inv0;
        const float p2 = s_acc[j][2] * inv1, p3 = s_acc[j][3] * inv1;
        const uint32_t o0 = prow + j * 16;
        const uint32_t o1 = o0 + 8 * 272;
        asm volatile("st.shared.b32 [%0], %1;" :: "r"(o0), "r"(pack_f16(p0, p1)) : "memory");
        asm volatile("st.shared.b32 [%0], %1;" :: "r"(o1), "r"(pack_f16(p2, p3)) : "memory");
    }
    CP_WAIT0();        // V landed (usually long ago)
    __syncthreads();   // P + V visible to ldmatrix across the block

    // ---- out = Ph · Vh ----
    const uint32_t ap = smb + (uint32_t)((w16 + (lane & 15)) * 272 + (lane >> 4) * 16);
    const int mat = lane >> 3;
    const uint32_t vb = smb + 36864u +
        (uint32_t)(((mat & 1) * 8 + (lane & 7)) * 144 + (mat >> 1) * 16);

    float o_acc[8][4];
#pragma unroll
    for (int j = 0; j < 8; j++)
#pragma unroll
        for (int q = 0; q < 4; q++) o_acc[j][q] = 0.0f;

#pragma unroll
    for (int kt = 0; kt < 8; kt++) {
        uint32_t Ph[4], Vf[4][4];
        ldsm_x4(Ph, ap + kt * 32);
#pragma unroll
        for (int vp = 0; vp < 4; vp++)
            ldsm_x4_t(Vf[vp], vb + (uint32_t)kt * 2304u + vp * 32u);
#pragma unroll
        for (int vp = 0; vp < 4; vp++) {
            mma_f16(o_acc[2 * vp],     Ph, Vf[vp][0], Vf[vp][1]);
            mma_f16(o_acc[2 * vp + 1], Ph, Vf[vp][2], Vf[vp][3]);
        }
    }

    // ---- epilogue: write fp16 attention output ----
    const int r0 = w16 + (lane >> 2);
    const size_t row0g = ((size_t)b * Mc + (size_t)seg * 128 + r0) * HIDc + h * 64;
    const size_t row1g = row0g + 8 * HIDc;
    const int dbase = 2 * (lane & 3);
#pragma unroll
    for (int j = 0; j < 8; j++) {
        const int d = 8 * j + dbase;
        *(uint32_t*)&g_attn_hi[row0g + d] = pack_f16(o_acc[j][0], o_acc[j][1]);
        *(uint32_t*)&g_attn_hi[row1g + d] = pack_f16(o_acc[j][2], o_acc[j][3]);
    }
}

// ===========================================================================
extern "C" void kernel_launch(void* const* d_in, const int* in_sizes, int n_in,
                              void* d_out, int out_size) {
    const float* x     = (const float*)d_in[0];
    const float* w_qkv = (const float*)d_in[1];
    const float* w_out = (const float*)d_in[2];
    const int*   hmap  = (const int*)d_in[3];
    float*       out   = (float*)d_out;

    cudaFuncSetAttribute(tgemm_kernel<0>, cudaFuncAttributeMaxDynamicSharedMemorySize, GEMM_SMEM);
    cudaFuncSetAttribute(tgemm_kernel<1>, cudaFuncAttributeMaxDynamicSharedMemorySize, GEMM_SMEM);
    cudaFuncSetAttribute(attn_kernel,     cudaFuncAttributeMaxDynamicSharedMemorySize, ATT_SMEM);

    __half *xhi, *wqh, *woh, *ahi;
    cudaGetSymbolAddress((void**)&xhi, g_xhi);
    cudaGetSymbolAddress((void**)&wqh, g_wqkv_hi);
    cudaGetSymbolAddress((void**)&woh, g_wout_hi);
    cudaGetSymbolAddress((void**)&ahi, g_attn_hi);

    // Fused pre-split: x, w_qkv, w_out -> fp16 in one launch (8 elems/thread)
    split3_kernel<<<(N8_TOTAL + 255) / 256, 256>>>(x, w_qkv, w_out);

    // QKV projection: 1-term, 128x128 tiles
    {
        dim3 grid(3072 / 128, (Bc * Mc) / 128);         // (24, 128)
        tgemm_kernel<0><<<grid, 256, GEMM_SMEM>>>(xhi, wqh, nullptr);
    }
    // Tensor-core Hilbert attention (split-gather overlap)
    {
        dim3 grid(NSEGc, Hc, Bc);
        attn_kernel<<<grid, 256, ATT_SMEM>>>(hmap);
    }
    // Output projection: 1-term, 128x128 tiles
    {
        dim3 grid(HIDc / 128, (Bc * Mc) / 128);         // (8, 128)
        tgemm_kernel<1><<<grid, 256, GEMM_SMEM>>>(ahi, woh, out);
    }
}

// round 17
// speedup vs baseline: 1.2217x; 1.0106x over previous
#include <cuda_runtime.h>
#include <cuda_fp16.h>
#include <cstdint>

// Problem constants
#define Bc    4
#define Mc    4096
#define HIDc  1024
#define Hc    16
#define HDc   64
#define NSEGc 32
#define SCALEc 0.125f

// ---------------------------------------------------------------------------
// Static device scratch (allocation-free per harness rules)
// ---------------------------------------------------------------------------
__device__ __half g_qkv_hi[(size_t)3 * Bc * Hc * Mc * HDc];  // [c][b][h][m][d]
__device__ __half g_xhi[(size_t)Bc * Mc * HIDc];
__device__ __half g_wqkv_hi[(size_t)3 * HIDc * HIDc];
__device__ __half g_wout_hi[(size_t)HIDc * HIDc];
__device__ __half g_attn_hi[(size_t)Bc * Mc * HIDc];

// ===========================================================================
// Helpers
// ===========================================================================
__device__ __forceinline__ uint32_t smem_u32(const void* p) {
    uint32_t a;
    asm("{ .reg .u64 t; cvta.to.shared.u64 t, %1; cvt.u32.u64 %0, t; }"
        : "=r"(a) : "l"(p));
    return a;
}

__device__ __forceinline__ void ldsm_x4(uint32_t* r, uint32_t addr) {
    asm volatile("ldmatrix.sync.aligned.m8n8.x4.shared.b16 {%0,%1,%2,%3}, [%4];"
                 : "=r"(r[0]), "=r"(r[1]), "=r"(r[2]), "=r"(r[3]) : "r"(addr));
}
__device__ __forceinline__ void ldsm_x4_t(uint32_t* r, uint32_t addr) {
    asm volatile("ldmatrix.sync.aligned.m8n8.x4.trans.shared.b16 {%0,%1,%2,%3}, [%4];"
                 : "=r"(r[0]), "=r"(r[1]), "=r"(r[2]), "=r"(r[3]) : "r"(addr));
}

__device__ __forceinline__ void mma_f16(float* c, const uint32_t* a,
                                        uint32_t b0, uint32_t b1) {
    asm volatile(
        "mma.sync.aligned.m16n8k16.row.col.f32.f16.f16.f32 "
        "{%0,%1,%2,%3}, {%4,%5,%6,%7}, {%8,%9}, {%0,%1,%2,%3};"
        : "+f"(c[0]), "+f"(c[1]), "+f"(c[2]), "+f"(c[3])
        : "r"(a[0]), "r"(a[1]), "r"(a[2]), "r"(a[3]), "r"(b0), "r"(b1));
}

__device__ __forceinline__ void cp_async16(uint32_t dst, const void* src) {
    asm volatile("cp.async.cg.shared.global [%0], [%1], 16;"
                 :: "r"(dst), "l"(src) : "memory");
}
#define CP_COMMIT() asm volatile("cp.async.commit_group;" ::: "memory")
#define CP_WAIT0()  asm volatile("cp.async.wait_group 0;" ::: "memory")
#define CP_WAIT1()  asm volatile("cp.async.wait_group 1;" ::: "memory")

__device__ __forceinline__ uint32_t pack_f16(float x, float y) {
    __half2 v = __halves2half2(__float2half_rn(x), __float2half_rn(y));
    return *reinterpret_cast<uint32_t*>(&v);
}

// ===========================================================================
// Fused pre-split kernel: all three fp32 tensors -> fp16, 8 elems/thread
// ===========================================================================
#define N4_X  ((Bc * Mc * HIDc) / 4)         // 4194304
#define N4_WQ ((3 * HIDc * HIDc) / 4)        // 786432
#define N4_WO ((HIDc * HIDc) / 4)            // 262144
#define N4_TOTAL (N4_X + N4_WQ + N4_WO)      // 5242880
#define N8_TOTAL (N4_TOTAL / 2)              // 2621440 (all counts even)

__global__ __launch_bounds__(256) void split3_kernel(
        const float* __restrict__ x, const float* __restrict__ wq,
        const float* __restrict__ wo) {
    const int i8 = blockIdx.x * 256 + threadIdx.x;
    if (i8 >= N8_TOTAL) return;
#pragma unroll
    for (int k = 0; k < 2; k++) {
        int j = 2 * i8 + k;
        const float* src;
        __half* dst;
        if (j < N4_X) {
            src = x;  dst = g_xhi;
        } else if (j < N4_X + N4_WQ) {
            j -= N4_X;         src = wq; dst = g_wqkv_hi;
        } else {
            j -= N4_X + N4_WQ; src = wo; dst = g_wout_hi;
        }
        const float4 v = ((const float4*)src)[j];
        ((__half2*)dst)[2 * j]     = __halves2half2(__float2half_rn(v.x), __float2half_rn(v.y));
        ((__half2*)dst)[2 * j + 1] = __halves2half2(__float2half_rn(v.z), __float2half_rn(v.w));
    }
}

// ===========================================================================
// fp16 1-term tensor GEMM: C = Ahi·Whi^T.
// 128x128 tile, K-chunk 64 (128 B rows, stride 144 B -> conflict-free),
// 256 threads, warps 4(m) x 2(n); 3-stage cp.async, 2 tiles/stage.
// Next-stage cp.async issue is spread across the first two k16 batches.
// MODE 0: epilogue scatters fp16 into g_qkv_hi.  MODE 1: fp32 row-major out.
// ===========================================================================
#define TK        64
#define NITER     (HIDc / TK)              // 16
#define LDSTR     72                       // fp16 elems per SMEM row (144 B)
#define TILE_HB   (128 * LDSTR * 2)        // 18432 B
#define STAGE_B   (2 * TILE_HB)            // 36864 B (A, B)
#define GEMM_SMEM (3 * STAGE_B)            // 110592 B

template <int MODE>
__global__ __launch_bounds__(256, 2) void tgemm_kernel(
        const __half* __restrict__ Ahi_g, const __half* __restrict__ Bhi_g,
        float* __restrict__ Cout) {
    extern __shared__ __align__(16) char smraw[];
    const uint32_t smb = smem_u32(smraw);

    const int tid  = threadIdx.x;
    const int wid  = tid >> 5;
    const int lane = tid & 31;
    const int row0 = blockIdx.y * 128;
    const int col0 = blockIdx.x * 128;
    const int warp_m = wid & 3;
    const int warp_n = wid >> 2;

    // ---- cp.async streams: 8 per thread (2 tiles x 4 chunks) ----
    const __half* src[8];
    uint32_t rel[8];
#pragma unroll
    for (int t = 0; t < 4; t++) {
        const int ci  = tid + 256 * t;
        const int row = ci >> 3;            // 0..127
        const int c16 = ci & 7;             // 16B chunk within 64-elem row
        const size_t offA = (size_t)(row0 + row) * HIDc + c16 * 8;
        const size_t offB = (size_t)(col0 + row) * HIDc + c16 * 8;
        const uint32_t so = (uint32_t)(row * (LDSTR * 2) + c16 * 16);
        src[2 * t + 0] = Ahi_g + offA;  rel[2 * t + 0] = so;
        src[2 * t + 1] = Bhi_g + offB;  rel[2 * t + 1] = TILE_HB + so;
    }

    const int sub = lane >> 3;
    const int r8  = lane & 7;
    uint32_t a_lm[2], b_lm[4];
#pragma unroll
    for (int mt = 0; mt < 2; mt++) {
        const int row = warp_m * 32 + mt * 16 + (sub & 1) * 8 + r8;
        a_lm[mt] = smb + row * (LDSTR * 2) + (sub >> 1) * 16;
    }
#pragma unroll
    for (int np = 0; np < 4; np++) {
        const int row = warp_n * 64 + np * 16 + (sub >> 1) * 8 + r8;
        b_lm[np] = smb + TILE_HB + row * (LDSTR * 2) + (sub & 1) * 16;
    }

    float acc[2][8][4];
#pragma unroll
    for (int i = 0; i < 2; i++)
#pragma unroll
        for (int j = 0; j < 8; j++)
#pragma unroll
            for (int q = 0; q < 4; q++) acc[i][j][q] = 0.0f;

    auto do_k16 = [&](uint32_t kb) {
        uint32_t Ah[2][4], Bf[4][4];
#pragma unroll
        for (int mt = 0; mt < 2; mt++) ldsm_x4(Ah[mt], a_lm[mt] + kb);
#pragma unroll
        for (int np = 0; np < 4; np++) ldsm_x4(Bf[np], b_lm[np] + kb);
#pragma unroll
        for (int mt = 0; mt < 2; mt++)
#pragma unroll
            for (int np = 0; np < 4; np++) {
                mma_f16(acc[mt][2 * np],     Ah[mt], Bf[np][0], Bf[np][1]);
                mma_f16(acc[mt][2 * np + 1], Ah[mt], Bf[np][2], Bf[np][3]);
            }
    };

    // ---- prologue: stages 0 and 1 ----
#pragma unroll
    for (int j = 0; j < 8; j++) cp_async16(smb + rel[j], src[j]);
    CP_COMMIT();
#pragma unroll
    for (int j = 0; j < 8; j++) {
        src[j] += TK;
        cp_async16(smb + STAGE_B + rel[j], src[j]);
    }
    CP_COMMIT();

    for (int it = 0; it < NITER; it++) {
        if (it + 1 < NITER) { CP_WAIT1(); } else { CP_WAIT0(); }
        __syncthreads();
        const uint32_t stg = (uint32_t)(it % 3) * STAGE_B;

        // first k16 immediately: tensor pipe fills right after the barrier
        do_k16(stg);

        // spread next-stage issue across two k16 batches
        const bool more = (it + 2 < NITER);
        const uint32_t nst = smb + (uint32_t)((it + 2) % 3) * STAGE_B;
        if (more) {
#pragma unroll
            for (int j = 0; j < 4; j++) {
                src[j] += TK;
                cp_async16(nst + rel[j], src[j]);
            }
        }
        do_k16(stg + 32);
        if (more) {
#pragma unroll
            for (int j = 4; j < 8; j++) {
                src[j] += TK;
                cp_async16(nst + rel[j], src[j]);
            }
            CP_COMMIT();
        }
        do_k16(stg + 64);
        do_k16(stg + 96);
    }

    // ---- epilogue ----
    const int rbase = row0 + warp_m * 32 + (lane >> 2);
    const int cbase = col0 + warp_n * 64 + 2 * (lane & 3);
#pragma unroll
    for (int mt = 0; mt < 2; mt++) {
#pragma unroll
        for (int nt = 0; nt < 8; nt++) {
            const int c = cbase + nt * 8;
#pragma unroll
            for (int half = 0; half < 2; half++) {
                const int r = rbase + mt * 16 + half * 8;
                const float vx = acc[mt][nt][2 * half];
                const float vy = acc[mt][nt][2 * half + 1];
                if (MODE == 0) {
                    const int b  = r >> 12;
                    const int m  = r & 4095;
                    const int cc = c >> 10;
                    const int h  = (c & 1023) >> 6;
                    const int d  = c & 63;
                    const size_t idx = (size_t)cc * (Bc * Hc * Mc * HDc) +
                        (((size_t)b * Hc + h) * Mc + m) * HDc + d;
                    *(uint32_t*)&g_qkv_hi[idx] = pack_f16(vx, vy);
                } else {
                    *(float2*)&Cout[(size_t)r * HIDc + c] = make_float2(vx, vy);
                }
            }
        }
    }
}

// ===========================================================================
// Tensor-core attention (fp16 1-term): one block per (seg,h,b), 8 warps.
// S = Qh·Kh^T, in-register masked softmax, out = P·Vh with P passed
// DIRECTLY from accumulator fragments to A-operand fragments (no SMEM
// round-trip): acc (m16n8) lane mapping == A-operand (m16k16) lane mapping
// when two adjacent n8 tiles are packed as {(c0,c1),(c2,c3)} pairs.
// SMEM: gather Qh@0, Kh@18432, Vh@36864.
// ===========================================================================
#define ATT_SMEM 55296

__global__ __launch_bounds__(256, 2) void attn_kernel(const int* __restrict__ hmap) {
    const int seg = blockIdx.x;
    const int h   = blockIdx.y;
    const int b   = blockIdx.z;

    extern __shared__ __align__(16) char smraw[];
    const uint32_t smb = smem_u32(smraw);
    __shared__ int toks[128];

    const int tid  = threadIdx.x;
    const int warp = tid >> 5;
    const int lane = tid & 31;

    if (tid < 128) toks[tid] = hmap[seg * 128 + tid];
    __syncthreads();

    // ---- gather group 0: Qh, Kh (8 chunks/thread) ----
#pragma unroll
    for (int n = 0; n < 8; n++) {
        const int c   = tid + 256 * n;
        const int p   = c >> 10;              // 0=Q, 1=K
        const int rem = c & 1023;
        const int row = rem >> 3;
        const int ch  = rem & 7;
        const __half* s = g_qkv_hi + (size_t)p * (Bc * Hc * Mc * HDc) +
            (((size_t)b * Hc + h) * Mc + toks[row]) * HDc + ch * 8;
        cp_async16(smb + (uint32_t)p * 18432u + (uint32_t)(row * 144 + ch * 16), s);
    }
    CP_COMMIT();
    // ---- gather group 1: Vh (4 chunks/thread) — lands during S phase ----
#pragma unroll
    for (int n = 0; n < 4; n++) {
        const int c   = tid + 256 * n;
        const int row = c >> 3;
        const int ch  = c & 7;
        const __half* s = g_qkv_hi + (size_t)2 * (Bc * Hc * Mc * HDc) +
            (((size_t)b * Hc + h) * Mc + toks[row]) * HDc + ch * 8;
        cp_async16(smb + 36864u + (uint32_t)(row * 144 + ch * 16), s);
    }
    CP_COMMIT();
    CP_WAIT1();    // Q/K landed; V may still be in flight
    __syncthreads();

    const int w16 = warp * 16;
    const int sub = lane >> 3;
    const int r8  = lane & 7;

    // ---- S = Qh Kh^T ----
    const uint32_t aq = smb + (uint32_t)((w16 + (sub & 1) * 8 + r8) * 144 + (sub >> 1) * 16);
    uint32_t bk[8];
#pragma unroll
    for (int np = 0; np < 8; np++)
        bk[np] = smb + 18432u + (uint32_t)((np * 16 + (sub >> 1) * 8 + r8) * 144 + (sub & 1) * 16);

    float s_acc[16][4];
#pragma unroll
    for (int j = 0; j < 16; j++)
#pragma unroll
        for (int q = 0; q < 4; q++) s_acc[j][q] = 0.0f;

#pragma unroll
    for (int kt = 0; kt < 4; kt++) {
        const uint32_t kb = kt * 32;
        uint32_t Ah[4], Bf[8][4];
        ldsm_x4(Ah, aq + kb);
#pragma unroll
        for (int np = 0; np < 8; np++) ldsm_x4(Bf[np], bk[np] + kb);
#pragma unroll
        for (int np = 0; np < 8; np++) {
            mma_f16(s_acc[2 * np],     Ah, Bf[np][0], Bf[np][1]);
            mma_f16(s_acc[2 * np + 1], Ah, Bf[np][2], Bf[np][3]);
        }
    }

    // ---- masked softmax in fragment registers ----
    const bool oddrow = ((lane >> 2) & 1) != 0;
    float mx0 = -1e30f, mx1 = -1e30f;
#pragma unroll
    for (int j = 0; j < 16; j++) {
#pragma unroll
        for (int q = 0; q < 4; q++) s_acc[j][q] *= SCALEc;
        if (oddrow) { s_acc[j][1] = -1e30f; s_acc[j][3] = -1e30f; }
        mx0 = fmaxf(mx0, fmaxf(s_acc[j][0], s_acc[j][1]));
        mx1 = fmaxf(mx1, fmaxf(s_acc[j][2], s_acc[j][3]));
    }
    mx0 = fmaxf(mx0, __shfl_xor_sync(0xffffffffu, mx0, 1));
    mx0 = fmaxf(mx0, __shfl_xor_sync(0xffffffffu, mx0, 2));
    mx1 = fmaxf(mx1, __shfl_xor_sync(0xffffffffu, mx1, 1));
    mx1 = fmaxf(mx1, __shfl_xor_sync(0xffffffffu, mx1, 2));

    float sum0 = 0.f, sum1 = 0.f;
#pragma unroll
    for (int j = 0; j < 16; j++) {
        s_acc[j][0] = __expf(s_acc[j][0] - mx0);
        s_acc[j][1] = __expf(s_acc[j][1] - mx0);
        s_acc[j][2] = __expf(s_acc[j][2] - mx1);
        s_acc[j][3] = __expf(s_acc[j][3] - mx1);
        sum0 += s_acc[j][0] + s_acc[j][1];
        sum1 += s_acc[j][2] + s_acc[j][3];
    }
    sum0 += __shfl_xor_sync(0xffffffffu, sum0, 1);
    sum0 += __shfl_xor_sync(0xffffffffu, sum0, 2);
    sum1 += __shfl_xor_sync(0xffffffffu, sum1, 1);
    sum1 += __shfl_xor_sync(0xffffffffu, sum1, 2);
    const float inv0 = 1.0f / sum0;
    const float inv1 = 1.0f / sum1;

    CP_WAIT0();        // V landed
    __syncthreads();   // V visible to all warps' ldmatrix

    // ---- out = P · Vh, P direct from fragments (no SMEM round-trip) ----
    const int mat = lane >> 3;
    const uint32_t vb = smb + 36864u +
        (uint32_t)(((mat & 1) * 8 + (lane & 7)) * 144 + (mat >> 1) * 16);

    float o_acc[8][4];
#pragma unroll
    for (int j = 0; j < 8; j++)
#pragma unroll
        for (int q = 0; q < 4; q++) o_acc[j][q] = 0.0f;

#pragma unroll
    for (int kt = 0; kt < 8; kt++) {
        uint32_t Ph[4], Vf[4][4];
        // accumulator->A-operand identity: tiles 2kt and 2kt+1 cover P cols
        // 16kt..16kt+15; (c0,c1)->rows g (inv0), (c2,c3)->rows g+8 (inv1)
        Ph[0] = pack_f16(s_acc[2 * kt][0] * inv0,     s_acc[2 * kt][1] * inv0);
        Ph[1] = pack_f16(s_acc[2 * kt][2] * inv1,     s_acc[2 * kt][3] * inv1);
        Ph[2] = pack_f16(s_acc[2 * kt + 1][0] * inv0, s_acc[2 * kt + 1][1] * inv0);
        Ph[3] = pack_f16(s_acc[2 * kt + 1][2] * inv1, s_acc[2 * kt + 1][3] * inv1);
#pragma unroll
        for (int vp = 0; vp < 4; vp++)
            ldsm_x4_t(Vf[vp], vb + (uint32_t)kt * 2304u + vp * 32u);
#pragma unroll
        for (int vp = 0; vp < 4; vp++) {
            mma_f16(o_acc[2 * vp],     Ph, Vf[vp][0], Vf[vp][1]);
            mma_f16(o_acc[2 * vp + 1], Ph, Vf[vp][2], Vf[vp][3]);
        }
    }

    // ---- epilogue: write fp16 attention output ----
    const int r0 = w16 + (lane >> 2);
    const size_t row0g = ((size_t)b * Mc + (size_t)seg * 128 + r0) * HIDc + h * 64;
    const size_t row1g = row0g + 8 * HIDc;
    const int dbase = 2 * (lane & 3);
#pragma unroll
    for (int j = 0; j < 8; j++) {
        const int d = 8 * j + dbase;
        *(uint32_t*)&g_attn_hi[row0g + d] = pack_f16(o_acc[j][0], o_acc[j][1]);
        *(uint32_t*)&g_attn_hi[row1g + d] = pack_f16(o_acc[j][2], o_acc[j][3]);
    }
}

// ===========================================================================
extern "C" void kernel_launch(void* const* d_in, const int* in_sizes, int n_in,
                              void* d_out, int out_size) {
    const float* x     = (const float*)d_in[0];
    const float* w_qkv = (const float*)d_in[1];
    const float* w_out = (const float*)d_in[2];
    const int*   hmap  = (const int*)d_in[3];
    float*       out   = (float*)d_out;

    cudaFuncSetAttribute(tgemm_kernel<0>, cudaFuncAttributeMaxDynamicSharedMemorySize, GEMM_SMEM);
    cudaFuncSetAttribute(tgemm_kernel<1>, cudaFuncAttributeMaxDynamicSharedMemorySize, GEMM_SMEM);
    cudaFuncSetAttribute(attn_kernel,     cudaFuncAttributeMaxDynamicSharedMemorySize, ATT_SMEM);

    __half *xhi, *wqh, *woh, *ahi;
    cudaGetSymbolAddress((void**)&xhi, g_xhi);
    cudaGetSymbolAddress((void**)&wqh, g_wqkv_hi);
    cudaGetSymbolAddress((void**)&woh, g_wout_hi);
    cudaGetSymbolAddress((void**)&ahi, g_attn_hi);

    // Fused pre-split: x, w_qkv, w_out -> fp16 in one launch (8 elems/thread)
    split3_kernel<<<(N8_TOTAL + 255) / 256, 256>>>(x, w_qkv, w_out);

    // QKV projection: 1-term, 128x128 tiles
    {
        dim3 grid(3072 / 128, (Bc * Mc) / 128);         // (24, 128)
        tgemm_kernel<0><<<grid, 256, GEMM_SMEM>>>(xhi, wqh, nullptr);
    }
    // Tensor-core Hilbert attention (fragment P passthrough)
    {
        dim3 grid(NSEGc, Hc, Bc);
        attn_kernel<<<grid, 256, ATT_SMEM>>>(hmap);
    }
    // Output projection: 1-term, 128x128 tiles
    {
        dim3 grid(HIDc / 128, (Bc * Mc) / 128);         // (8, 128)
        tgemm_kernel<1><<<grid, 256, GEMM_SMEM>>>(ahi, woh, out);
    }
}